// round 1
// baseline (speedup 1.0000x reference)
#include <cuda_runtime.h>
#include <cstdint>

#define BB 256
#define HH 512
#define SS 512
#define H3 1536

// ---------------- scratch (no allocations allowed) ----------------
__device__ float g_hnew[BB * HH];
__device__ float g_hc[BB * HH];
__device__ float g_scores[BB * SS];
__device__ float g_attns[BB * SS];
__device__ float g_context[BB * HH];
__device__ float g_cd2[BB * HH];

// ---------------- f32x2 packed-FMA helpers (sm_103a FFMA2) ----------------
__device__ __forceinline__ unsigned long long dup_f32x2(float x) {
    unsigned long long r;
    unsigned u = __float_as_uint(x);
    asm("mov.b64 %0, {%1,%2};" : "=l"(r) : "r"(u), "r"(u));
    return r;
}
__device__ __forceinline__ void fma_f32x2(unsigned long long& d,
                                          unsigned long long a,
                                          unsigned long long b) {
    asm("fma.rn.f32x2 %0, %1, %2, %0;" : "+l"(d) : "l"(a), "l"(b));
}
__device__ __forceinline__ float2 unpack_f32x2(unsigned long long v) {
    unsigned lo, hi;
    asm("mov.b64 {%0,%1}, %2;" : "=r"(lo), "=r"(hi) : "l"(v));
    return make_float2(__uint_as_float(lo), __uint_as_float(hi));
}

// Accurate-enough tanh independent of fast-math flags (~1e-6 rel).
__device__ __forceinline__ float my_tanh(float x) {
    float ax = fabsf(x);
    float e = __expf(-2.0f * ax);           // MUFU.EX2 path, ~2 ulp
    float r = (1.0f - e) / (1.0f + e);
    return copysignf(r, x);
}
__device__ __forceinline__ float my_sigmoid(float x) {
    return 1.0f / (1.0f + __expf(-x));
}

// ---------------- kernel 1: embedding + GRU step ----------------
__global__ void gru_kernel(const float* __restrict__ last_output,
                           const float* __restrict__ last_hidden,
                           const float* __restrict__ emb_W,
                           const float* __restrict__ emb_b,
                           const float* __restrict__ Wih,
                           const float* __restrict__ Whh,
                           const float* __restrict__ bih,
                           const float* __restrict__ bhh,
                           float* __restrict__ hidden_out) {
    int b = blockIdx.x;
    int t = threadIdx.x;  // 256 threads
    __shared__ float sx[HH], sh[HH];
    __shared__ float sgx[H3], sgh[H3];

    float o0 = last_output[b * 2 + 0];
    float o1 = last_output[b * 2 + 1];
    for (int j = t; j < HH; j += 256) {
        sx[j] = o0 * emb_W[j * 2 + 0] + o1 * emb_W[j * 2 + 1] + emb_b[j];
        sh[j] = last_hidden[b * HH + j];
    }
    __syncthreads();

    for (int j = t; j < H3; j += 256) {
        float ax = bih[j], ah = bhh[j];
        const float4* wi = (const float4*)(Wih + (size_t)j * HH);
        const float4* wh = (const float4*)(Whh + (size_t)j * HH);
#pragma unroll 4
        for (int k4 = 0; k4 < HH / 4; k4++) {
            float4 a = wi[k4];
            float4 c = wh[k4];
            int k = k4 * 4;
            ax += a.x * sx[k] + a.y * sx[k + 1] + a.z * sx[k + 2] + a.w * sx[k + 3];
            ah += c.x * sh[k] + c.y * sh[k + 1] + c.z * sh[k + 2] + c.w * sh[k + 3];
        }
        sgx[j] = ax;
        sgh[j] = ah;
    }
    __syncthreads();

    for (int j = t; j < HH; j += 256) {
        float r = my_sigmoid(sgx[j] + sgh[j]);
        float z = my_sigmoid(sgx[HH + j] + sgh[HH + j]);
        float n = my_tanh(sgx[2 * HH + j] + r * sgh[2 * HH + j]);
        float hn = (1.0f - z) * n + z * sh[j];
        g_hnew[b * HH + j] = hn;
        hidden_out[b * HH + j] = hn;  // second output of reference
    }
}

// ---------------- kernel: out[b,h] = sum_k M[h, off+k] * vec[b,k] ----------------
__global__ void matvec_kernel(const float* __restrict__ M, int ldm, int off,
                              const float* __restrict__ vec,
                              float* __restrict__ out) {
    int b = blockIdx.y;
    int h0 = blockIdx.x * 64;
    int t = threadIdx.x;  // 256 threads, 4 per row
    __shared__ float sv[HH];
    for (int k = t; k < HH; k += 256) sv[k] = vec[b * HH + k];
    __syncthreads();

    int hl = t >> 2, l4 = t & 3;
    int h = h0 + hl;
    const float* m = M + (size_t)h * ldm + off;
    float acc = 0.0f;
    for (int k = l4 * 4; k < HH; k += 16) {
        float4 mv = *(const float4*)(m + k);
        acc += mv.x * sv[k] + mv.y * sv[k + 1] + mv.z * sv[k + 2] + mv.w * sv[k + 3];
    }
    acc += __shfl_xor_sync(0xffffffffu, acc, 1);
    acc += __shfl_xor_sync(0xffffffffu, acc, 2);
    if (l4 == 0) out[b * HH + h] = acc;
}

// ---------------- the big fused kernel ----------------
// out[b,s] = sum_h vvec[h] * tanh( (A1@X1)[h,s] (+ (A2@X2)[h,s]) + addvec[b,h] )
// A1 = A[:, 0:512], A2 = A[:, offB:offB+512] (row stride lda).
// X = [B,H,S] batched, contraction over H (k) for each (b,s) column.
template <bool DUAL>
__global__ __launch_bounds__(256, 2) void pointer_kernel(
    const float* __restrict__ A, int lda, int offB,
    const float* __restrict__ Xs, const float* __restrict__ Xd,
    const float* __restrict__ addvec, const float* __restrict__ vvec,
    float* __restrict__ outp) {
    int b = blockIdx.y;
    int s0 = blockIdx.x * 128;
    int t = threadIdx.x;
    int ty = t >> 4;   // 0..15 (rows)
    int tx = t & 15;   // 0..15 (cols)

    __shared__ __align__(16) float Aa[16][128];
    __shared__ __align__(16) float Ab[16][128];
    __shared__ __align__(16) float Bs[16][128];
    __shared__ __align__(16) float Bd[16][128];
    __shared__ float red[16][128];

    const float* Xsb = Xs + (size_t)b * HH * SS;
    const float* Xdb = DUAL ? (Xd + (size_t)b * HH * SS) : Xs;

    float p[8];
#pragma unroll
    for (int j = 0; j < 8; j++) p[j] = 0.0f;

    for (int hch = 0; hch < HH; hch += 128) {
        unsigned long long acc[8][4];
#pragma unroll
        for (int i = 0; i < 8; i++)
#pragma unroll
            for (int j = 0; j < 4; j++) acc[i][j] = 0ull;

        for (int k0 = 0; k0 < HH; k0 += 16) {
            // A tiles, stored transposed: Aa[k][h]
#pragma unroll
            for (int r = 0; r < 2; r++) {
                int id = t + r * 256;      // 0..511
                int h = id >> 2;           // 0..127
                int q = id & 3;            // k-quad
                const float* ap = A + (size_t)(hch + h) * lda + k0 + q * 4;
                float4 a4 = *(const float4*)ap;
                Aa[q * 4 + 0][h] = a4.x;
                Aa[q * 4 + 1][h] = a4.y;
                Aa[q * 4 + 2][h] = a4.z;
                Aa[q * 4 + 3][h] = a4.w;
                if (DUAL) {
                    float4 c4 = *(const float4*)(ap + offB);
                    Ab[q * 4 + 0][h] = c4.x;
                    Ab[q * 4 + 1][h] = c4.y;
                    Ab[q * 4 + 2][h] = c4.z;
                    Ab[q * 4 + 3][h] = c4.w;
                }
            }
            // B tiles: Bs[k][s]
#pragma unroll
            for (int r = 0; r < 2; r++) {
                int id = t + r * 256;  // 0..511
                int k = id >> 5;       // 0..15
                int m = id & 31;       // quad within the 128-col row
                *(float4*)&Bs[k][m * 4] =
                    *(const float4*)(Xsb + (size_t)(k0 + k) * SS + s0 + m * 4);
                if (DUAL)
                    *(float4*)&Bd[k][m * 4] =
                        *(const float4*)(Xdb + (size_t)(k0 + k) * SS + s0 + m * 4);
            }
            __syncthreads();

#pragma unroll
            for (int kk = 0; kk < 16; kk++) {
                float4 a0 = *(const float4*)&Aa[kk][ty * 8];
                float4 a1 = *(const float4*)&Aa[kk][ty * 8 + 4];
                ulonglong2 bs0 = *(const ulonglong2*)&Bs[kk][tx * 8];
                ulonglong2 bs1 = *(const ulonglong2*)&Bs[kk][tx * 8 + 4];
                float ar[8] = {a0.x, a0.y, a0.z, a0.w, a1.x, a1.y, a1.z, a1.w};
#pragma unroll
                for (int i = 0; i < 8; i++) {
                    unsigned long long ad = dup_f32x2(ar[i]);
                    fma_f32x2(acc[i][0], ad, bs0.x);
                    fma_f32x2(acc[i][1], ad, bs0.y);
                    fma_f32x2(acc[i][2], ad, bs1.x);
                    fma_f32x2(acc[i][3], ad, bs1.y);
                }
                if (DUAL) {
                    float4 c0 = *(const float4*)&Ab[kk][ty * 8];
                    float4 c1 = *(const float4*)&Ab[kk][ty * 8 + 4];
                    ulonglong2 bd0 = *(const ulonglong2*)&Bd[kk][tx * 8];
                    ulonglong2 bd1 = *(const ulonglong2*)&Bd[kk][tx * 8 + 4];
                    float ar2[8] = {c0.x, c0.y, c0.z, c0.w, c1.x, c1.y, c1.z, c1.w};
#pragma unroll
                    for (int i = 0; i < 8; i++) {
                        unsigned long long ad = dup_f32x2(ar2[i]);
                        fma_f32x2(acc[i][0], ad, bd0.x);
                        fma_f32x2(acc[i][1], ad, bd0.y);
                        fma_f32x2(acc[i][2], ad, bd1.x);
                        fma_f32x2(acc[i][3], ad, bd1.y);
                    }
                }
            }
            __syncthreads();
        }

        // epilogue for this h-chunk: add bias, tanh, weight by vvec, fold into p
#pragma unroll
        for (int i = 0; i < 8; i++) {
            int h = hch + ty * 8 + i;
            float av = addvec[b * HH + h];
            float vv = vvec[h];
#pragma unroll
            for (int jp = 0; jp < 4; jp++) {
                float2 c = unpack_f32x2(acc[i][jp]);
                p[2 * jp + 0] += vv * my_tanh(c.x + av);
                p[2 * jp + 1] += vv * my_tanh(c.y + av);
            }
        }
    }

    // reduce partial sums over ty (16-way) in smem
#pragma unroll
    for (int j = 0; j < 8; j++) red[ty][tx * 8 + j] = p[j];
    __syncthreads();
    for (int off = 8; off > 0; off >>= 1) {
        if (ty < off) {
#pragma unroll
            for (int j = 0; j < 8; j++)
                red[ty][tx * 8 + j] += red[ty + off][tx * 8 + j];
        }
        __syncthreads();
    }
    if (ty == 0) {
#pragma unroll
        for (int j = 0; j < 8; j++)
            outp[b * SS + s0 + tx * 8 + j] = red[0][tx * 8 + j];
    }
}

// ---------------- softmax over S per batch row ----------------
__global__ void softmax_kernel(const float* __restrict__ scores,
                               float* __restrict__ attns) {
    int b = blockIdx.x;
    int t = threadIdx.x;  // 256
    __shared__ float sm[256];
    float v0 = scores[b * SS + t];
    float v1 = scores[b * SS + 256 + t];
    sm[t] = fmaxf(v0, v1);
    __syncthreads();
    for (int off = 128; off > 0; off >>= 1) {
        if (t < off) sm[t] = fmaxf(sm[t], sm[t + off]);
        __syncthreads();
    }
    float mx = sm[0];
    __syncthreads();
    float e0 = __expf(v0 - mx);
    float e1 = __expf(v1 - mx);
    sm[t] = e0 + e1;
    __syncthreads();
    for (int off = 128; off > 0; off >>= 1) {
        if (t < off) sm[t] += sm[t + off];
        __syncthreads();
    }
    float inv = 1.0f / sm[0];
    attns[b * SS + t] = e0 * inv;
    attns[b * SS + 256 + t] = e1 * inv;
}

// ---------------- context[b,h] = sum_s attns[b,s] * static[b,h,s] ----------------
__global__ void context_kernel(const float* __restrict__ st,
                               const float* __restrict__ attns,
                               float* __restrict__ ctx) {
    int b = blockIdx.y;
    int h0 = blockIdx.x * 8;
    int w = threadIdx.x >> 5, l = threadIdx.x & 31;
    __shared__ float sa[SS];
    for (int s = threadIdx.x; s < SS; s += 256) sa[s] = attns[b * SS + s];
    __syncthreads();
    int h = h0 + w;
    const float* row = st + (size_t)b * HH * SS + (size_t)h * SS;
    float acc = 0.0f;
    for (int s = l * 4; s < SS; s += 128) {
        float4 r4 = *(const float4*)(row + s);
        acc += r4.x * sa[s] + r4.y * sa[s + 1] + r4.z * sa[s + 2] + r4.w * sa[s + 3];
    }
#pragma unroll
    for (int off = 16; off > 0; off >>= 1)
        acc += __shfl_xor_sync(0xffffffffu, acc, off);
    if (l == 0) ctx[b * HH + h] = acc;
}

// ---------------- launch ----------------
extern "C" void kernel_launch(void* const* d_in, const int* in_sizes, int n_in,
                              void* d_out, int out_size) {
    const float* st     = (const float*)d_in[0];
    const float* dy     = (const float*)d_in[1];
    const float* lo     = (const float*)d_in[2];
    const float* lh     = (const float*)d_in[3];
    const float* embW   = (const float*)d_in[4];
    const float* embb   = (const float*)d_in[5];
    const float* Wih    = (const float*)d_in[6];
    const float* Whh    = (const float*)d_in[7];
    const float* bih    = (const float*)d_in[8];
    const float* bhh    = (const float*)d_in[9];
    const float* attn_v = (const float*)d_in[10];
    const float* attn_W = (const float*)d_in[11];
    const float* dec_v  = (const float*)d_in[12];
    const float* dec_W  = (const float*)d_in[13];
    float* out = (float*)d_out;  // [B*S] outputs, then [B*H] hidden

    float *p_hnew, *p_hc, *p_scores, *p_attns, *p_ctx, *p_cd2;
    cudaGetSymbolAddress((void**)&p_hnew, g_hnew);
    cudaGetSymbolAddress((void**)&p_hc, g_hc);
    cudaGetSymbolAddress((void**)&p_scores, g_scores);
    cudaGetSymbolAddress((void**)&p_attns, g_attns);
    cudaGetSymbolAddress((void**)&p_ctx, g_context);
    cudaGetSymbolAddress((void**)&p_cd2, g_cd2);

    // 1. embedding + GRU -> h_new (also writes hidden output)
    gru_kernel<<<BB, 256>>>(lo, lh, embW, embb, Wih, Whh, bih, bhh, out + BB * SS);

    // 2. hc[b,h] = h_new @ Wc^T  (Wc = attn_W[:, 2H:3H])
    matvec_kernel<<<dim3(8, BB), 256>>>(attn_W, H3, 2 * HH, p_hnew, p_hc);

    // 3. scores[b,s] = v . tanh(Wa@st + Wb@dy + hc)
    pointer_kernel<true><<<dim3(SS / 128, BB), 256>>>(attn_W, H3, HH, st, dy,
                                                      p_hc, attn_v, p_scores);

    // 4. softmax over s
    softmax_kernel<<<BB, 256>>>(p_scores, p_attns);

    // 5. context
    context_kernel<<<dim3(HH / 8, BB), 256>>>(st, p_attns, p_ctx);

    // 6. cd2[b,h] = context @ Wd2^T (Wd2 = dec_W[:, H:2H])
    matvec_kernel<<<dim3(8, BB), 256>>>(dec_W, 2 * HH, HH, p_ctx, p_cd2);

    // 7. outputs[b,s] = dec_v . tanh(Wd1@st + cd2)
    pointer_kernel<false><<<dim3(SS / 128, BB), 256>>>(dec_W, 2 * HH, 0, st,
                                                       nullptr, p_cd2, dec_v, out);
}

// round 2
// speedup vs baseline: 1.0012x; 1.0012x over previous
#include <cuda_runtime.h>
#include <cstdint>

#define BB 256
#define HH 512
#define SS 512
#define H3 1536

// ---------------- scratch (no allocations allowed) ----------------
__device__ float g_hnew[BB * HH];
__device__ float g_hc[BB * HH];
__device__ float g_scores[BB * SS];
__device__ float g_attns[BB * SS];
__device__ float g_context[BB * HH];
__device__ float g_cd2[BB * HH];

// ---------------- f32x2 packed-FMA helpers (sm_103a FFMA2) ----------------
__device__ __forceinline__ unsigned long long dup_f32x2(float x) {
    unsigned long long r;
    unsigned u = __float_as_uint(x);
    asm("mov.b64 %0, {%1,%2};" : "=l"(r) : "r"(u), "r"(u));
    return r;
}
__device__ __forceinline__ void fma_f32x2(unsigned long long& d,
                                          unsigned long long a,
                                          unsigned long long b) {
    asm("fma.rn.f32x2 %0, %1, %2, %0;" : "+l"(d) : "l"(a), "l"(b));
}
__device__ __forceinline__ float2 unpack_f32x2(unsigned long long v) {
    unsigned lo, hi;
    asm("mov.b64 {%0,%1}, %2;" : "=r"(lo), "=r"(hi) : "l"(v));
    return make_float2(__uint_as_float(lo), __uint_as_float(hi));
}

// Accurate-enough tanh independent of fast-math flags (~1e-6 rel).
__device__ __forceinline__ float my_tanh(float x) {
    float ax = fabsf(x);
    float e = __expf(-2.0f * ax);           // MUFU.EX2 path, ~2 ulp
    float r = (1.0f - e) / (1.0f + e);
    return copysignf(r, x);
}
__device__ __forceinline__ float my_sigmoid(float x) {
    return 1.0f / (1.0f + __expf(-x));
}

// ---------------- kernel 1: embedding + GRU step ----------------
__global__ void gru_kernel(const float* __restrict__ last_output,
                           const float* __restrict__ last_hidden,
                           const float* __restrict__ emb_W,
                           const float* __restrict__ emb_b,
                           const float* __restrict__ Wih,
                           const float* __restrict__ Whh,
                           const float* __restrict__ bih,
                           const float* __restrict__ bhh,
                           float* __restrict__ hidden_out) {
    int b = blockIdx.x;
    int t = threadIdx.x;  // 256 threads
    __shared__ float sx[HH], sh[HH];
    __shared__ float sgx[H3], sgh[H3];

    float o0 = last_output[b * 2 + 0];
    float o1 = last_output[b * 2 + 1];
    for (int j = t; j < HH; j += 256) {
        sx[j] = o0 * emb_W[j * 2 + 0] + o1 * emb_W[j * 2 + 1] + emb_b[j];
        sh[j] = last_hidden[b * HH + j];
    }
    __syncthreads();

    for (int j = t; j < H3; j += 256) {
        float ax = bih[j], ah = bhh[j];
        const float4* wi = (const float4*)(Wih + (size_t)j * HH);
        const float4* wh = (const float4*)(Whh + (size_t)j * HH);
#pragma unroll 4
        for (int k4 = 0; k4 < HH / 4; k4++) {
            float4 a = wi[k4];
            float4 c = wh[k4];
            int k = k4 * 4;
            ax += a.x * sx[k] + a.y * sx[k + 1] + a.z * sx[k + 2] + a.w * sx[k + 3];
            ah += c.x * sh[k] + c.y * sh[k + 1] + c.z * sh[k + 2] + c.w * sh[k + 3];
        }
        sgx[j] = ax;
        sgh[j] = ah;
    }
    __syncthreads();

    for (int j = t; j < HH; j += 256) {
        float r = my_sigmoid(sgx[j] + sgh[j]);
        float z = my_sigmoid(sgx[HH + j] + sgh[HH + j]);
        float n = my_tanh(sgx[2 * HH + j] + r * sgh[2 * HH + j]);
        float hn = (1.0f - z) * n + z * sh[j];
        g_hnew[b * HH + j] = hn;
        hidden_out[b * HH + j] = hn;  // second output of reference
    }
}

// ---------------- kernel: out[b,h] = sum_k M[h, off+k] * vec[b,k] ----------------
__global__ void matvec_kernel(const float* __restrict__ M, int ldm, int off,
                              const float* __restrict__ vec,
                              float* __restrict__ out) {
    int b = blockIdx.y;
    int h0 = blockIdx.x * 64;
    int t = threadIdx.x;  // 256 threads, 4 per row
    __shared__ float sv[HH];
    for (int k = t; k < HH; k += 256) sv[k] = vec[b * HH + k];
    __syncthreads();

    int hl = t >> 2, l4 = t & 3;
    int h = h0 + hl;
    const float* m = M + (size_t)h * ldm + off;
    float acc = 0.0f;
    for (int k = l4 * 4; k < HH; k += 16) {
        float4 mv = *(const float4*)(m + k);
        acc += mv.x * sv[k] + mv.y * sv[k + 1] + mv.z * sv[k + 2] + mv.w * sv[k + 3];
    }
    acc += __shfl_xor_sync(0xffffffffu, acc, 1);
    acc += __shfl_xor_sync(0xffffffffu, acc, 2);
    if (l4 == 0) out[b * HH + h] = acc;
}

// ---------------- the big fused kernel ----------------
// out[b,s] = sum_h vvec[h] * tanh( (A1@X1)[h,s] (+ (A2@X2)[h,s]) + addvec[b,h] )
// A1 = A[:, 0:512], A2 = A[:, offB:offB+512] (row stride lda).
// X = [B,H,S] batched, contraction over H (k) for each (b,s) column.
template <bool DUAL>
__global__ __launch_bounds__(256, 2) void pointer_kernel(
    const float* __restrict__ A, int lda, int offB,
    const float* __restrict__ Xs, const float* __restrict__ Xd,
    const float* __restrict__ addvec, const float* __restrict__ vvec,
    float* __restrict__ outp) {
    int b = blockIdx.y;
    int s0 = blockIdx.x * 128;
    int t = threadIdx.x;
    int ty = t >> 4;   // 0..15 (rows)
    int tx = t & 15;   // 0..15 (cols)

    __shared__ __align__(16) float Aa[16][128];
    __shared__ __align__(16) float Ab[16][128];
    __shared__ __align__(16) float Bs[16][128];
    __shared__ __align__(16) float Bd[16][128];
    __shared__ float red[16][128];

    const float* Xsb = Xs + (size_t)b * HH * SS;
    const float* Xdb = DUAL ? (Xd + (size_t)b * HH * SS) : Xs;

    float p[8];
#pragma unroll
    for (int j = 0; j < 8; j++) p[j] = 0.0f;

    for (int hch = 0; hch < HH; hch += 128) {
        unsigned long long acc[8][4];
#pragma unroll
        for (int i = 0; i < 8; i++)
#pragma unroll
            for (int j = 0; j < 4; j++) acc[i][j] = 0ull;

        for (int k0 = 0; k0 < HH; k0 += 16) {
            // A tiles, stored transposed: Aa[k][h]
#pragma unroll
            for (int r = 0; r < 2; r++) {
                int id = t + r * 256;      // 0..511
                int h = id >> 2;           // 0..127
                int q = id & 3;            // k-quad
                const float* ap = A + (size_t)(hch + h) * lda + k0 + q * 4;
                float4 a4 = *(const float4*)ap;
                Aa[q * 4 + 0][h] = a4.x;
                Aa[q * 4 + 1][h] = a4.y;
                Aa[q * 4 + 2][h] = a4.z;
                Aa[q * 4 + 3][h] = a4.w;
                if (DUAL) {
                    float4 c4 = *(const float4*)(ap + offB);
                    Ab[q * 4 + 0][h] = c4.x;
                    Ab[q * 4 + 1][h] = c4.y;
                    Ab[q * 4 + 2][h] = c4.z;
                    Ab[q * 4 + 3][h] = c4.w;
                }
            }
            // B tiles: Bs[k][s]
#pragma unroll
            for (int r = 0; r < 2; r++) {
                int id = t + r * 256;  // 0..511
                int k = id >> 5;       // 0..15
                int m = id & 31;       // quad within the 128-col row
                *(float4*)&Bs[k][m * 4] =
                    *(const float4*)(Xsb + (size_t)(k0 + k) * SS + s0 + m * 4);
                if (DUAL)
                    *(float4*)&Bd[k][m * 4] =
                        *(const float4*)(Xdb + (size_t)(k0 + k) * SS + s0 + m * 4);
            }
            __syncthreads();

#pragma unroll
            for (int kk = 0; kk < 16; kk++) {
                float4 a0 = *(const float4*)&Aa[kk][ty * 8];
                float4 a1 = *(const float4*)&Aa[kk][ty * 8 + 4];
                ulonglong2 bs0 = *(const ulonglong2*)&Bs[kk][tx * 8];
                ulonglong2 bs1 = *(const ulonglong2*)&Bs[kk][tx * 8 + 4];
                float ar[8] = {a0.x, a0.y, a0.z, a0.w, a1.x, a1.y, a1.z, a1.w};
#pragma unroll
                for (int i = 0; i < 8; i++) {
                    unsigned long long ad = dup_f32x2(ar[i]);
                    fma_f32x2(acc[i][0], ad, bs0.x);
                    fma_f32x2(acc[i][1], ad, bs0.y);
                    fma_f32x2(acc[i][2], ad, bs1.x);
                    fma_f32x2(acc[i][3], ad, bs1.y);
                }
                if (DUAL) {
                    float4 c0 = *(const float4*)&Ab[kk][ty * 8];
                    float4 c1 = *(const float4*)&Ab[kk][ty * 8 + 4];
                    ulonglong2 bd0 = *(const ulonglong2*)&Bd[kk][tx * 8];
                    ulonglong2 bd1 = *(const ulonglong2*)&Bd[kk][tx * 8 + 4];
                    float ar2[8] = {c0.x, c0.y, c0.z, c0.w, c1.x, c1.y, c1.z, c1.w};
#pragma unroll
                    for (int i = 0; i < 8; i++) {
                        unsigned long long ad = dup_f32x2(ar2[i]);
                        fma_f32x2(acc[i][0], ad, bd0.x);
                        fma_f32x2(acc[i][1], ad, bd0.y);
                        fma_f32x2(acc[i][2], ad, bd1.x);
                        fma_f32x2(acc[i][3], ad, bd1.y);
                    }
                }
            }
            __syncthreads();
        }

        // epilogue for this h-chunk: add bias, tanh, weight by vvec, fold into p
#pragma unroll
        for (int i = 0; i < 8; i++) {
            int h = hch + ty * 8 + i;
            float av = addvec[b * HH + h];
            float vv = vvec[h];
#pragma unroll
            for (int jp = 0; jp < 4; jp++) {
                float2 c = unpack_f32x2(acc[i][jp]);
                p[2 * jp + 0] += vv * my_tanh(c.x + av);
                p[2 * jp + 1] += vv * my_tanh(c.y + av);
            }
        }
    }

    // reduce partial sums over ty (16-way) in smem
#pragma unroll
    for (int j = 0; j < 8; j++) red[ty][tx * 8 + j] = p[j];
    __syncthreads();
    for (int off = 8; off > 0; off >>= 1) {
        if (ty < off) {
#pragma unroll
            for (int j = 0; j < 8; j++)
                red[ty][tx * 8 + j] += red[ty + off][tx * 8 + j];
        }
        __syncthreads();
    }
    if (ty == 0) {
#pragma unroll
        for (int j = 0; j < 8; j++)
            outp[b * SS + s0 + tx * 8 + j] = red[0][tx * 8 + j];
    }
}

// ---------------- softmax over S per batch row ----------------
__global__ void softmax_kernel(const float* __restrict__ scores,
                               float* __restrict__ attns) {
    int b = blockIdx.x;
    int t = threadIdx.x;  // 256
    __shared__ float sm[256];
    float v0 = scores[b * SS + t];
    float v1 = scores[b * SS + 256 + t];
    sm[t] = fmaxf(v0, v1);
    __syncthreads();
    for (int off = 128; off > 0; off >>= 1) {
        if (t < off) sm[t] = fmaxf(sm[t], sm[t + off]);
        __syncthreads();
    }
    float mx = sm[0];
    __syncthreads();
    float e0 = __expf(v0 - mx);
    float e1 = __expf(v1 - mx);
    sm[t] = e0 + e1;
    __syncthreads();
    for (int off = 128; off > 0; off >>= 1) {
        if (t < off) sm[t] += sm[t + off];
        __syncthreads();
    }
    float inv = 1.0f / sm[0];
    attns[b * SS + t] = e0 * inv;
    attns[b * SS + 256 + t] = e1 * inv;
}

// ---------------- context[b,h] = sum_s attns[b,s] * static[b,h,s] ----------------
__global__ void context_kernel(const float* __restrict__ st,
                               const float* __restrict__ attns,
                               float* __restrict__ ctx) {
    int b = blockIdx.y;
    int h0 = blockIdx.x * 8;
    int w = threadIdx.x >> 5, l = threadIdx.x & 31;
    __shared__ float sa[SS];
    for (int s = threadIdx.x; s < SS; s += 256) sa[s] = attns[b * SS + s];
    __syncthreads();
    int h = h0 + w;
    const float* row = st + (size_t)b * HH * SS + (size_t)h * SS;
    float acc = 0.0f;
    for (int s = l * 4; s < SS; s += 128) {
        float4 r4 = *(const float4*)(row + s);
        acc += r4.x * sa[s] + r4.y * sa[s + 1] + r4.z * sa[s + 2] + r4.w * sa[s + 3];
    }
#pragma unroll
    for (int off = 16; off > 0; off >>= 1)
        acc += __shfl_xor_sync(0xffffffffu, acc, off);
    if (l == 0) ctx[b * HH + h] = acc;
}

// ---------------- launch ----------------
extern "C" void kernel_launch(void* const* d_in, const int* in_sizes, int n_in,
                              void* d_out, int out_size) {
    const float* st     = (const float*)d_in[0];
    const float* dy     = (const float*)d_in[1];
    const float* lo     = (const float*)d_in[2];
    const float* lh     = (const float*)d_in[3];
    const float* embW   = (const float*)d_in[4];
    const float* embb   = (const float*)d_in[5];
    const float* Wih    = (const float*)d_in[6];
    const float* Whh    = (const float*)d_in[7];
    const float* bih    = (const float*)d_in[8];
    const float* bhh    = (const float*)d_in[9];
    const float* attn_v = (const float*)d_in[10];
    const float* attn_W = (const float*)d_in[11];
    const float* dec_v  = (const float*)d_in[12];
    const float* dec_W  = (const float*)d_in[13];
    float* out = (float*)d_out;  // [B*S] outputs, then [B*H] hidden

    float *p_hnew, *p_hc, *p_scores, *p_attns, *p_ctx, *p_cd2;
    cudaGetSymbolAddress((void**)&p_hnew, g_hnew);
    cudaGetSymbolAddress((void**)&p_hc, g_hc);
    cudaGetSymbolAddress((void**)&p_scores, g_scores);
    cudaGetSymbolAddress((void**)&p_attns, g_attns);
    cudaGetSymbolAddress((void**)&p_ctx, g_context);
    cudaGetSymbolAddress((void**)&p_cd2, g_cd2);

    // 1. embedding + GRU -> h_new (also writes hidden output)
    gru_kernel<<<BB, 256>>>(lo, lh, embW, embb, Wih, Whh, bih, bhh, out + BB * SS);

    // 2. hc[b,h] = h_new @ Wc^T  (Wc = attn_W[:, 2H:3H])
    matvec_kernel<<<dim3(8, BB), 256>>>(attn_W, H3, 2 * HH, p_hnew, p_hc);

    // 3. scores[b,s] = v . tanh(Wa@st + Wb@dy + hc)
    pointer_kernel<true><<<dim3(SS / 128, BB), 256>>>(attn_W, H3, HH, st, dy,
                                                      p_hc, attn_v, p_scores);

    // 4. softmax over s
    softmax_kernel<<<BB, 256>>>(p_scores, p_attns);

    // 5. context
    context_kernel<<<dim3(HH / 8, BB), 256>>>(st, p_attns, p_ctx);

    // 6. cd2[b,h] = context @ Wd2^T (Wd2 = dec_W[:, H:2H])
    matvec_kernel<<<dim3(8, BB), 256>>>(dec_W, 2 * HH, HH, p_ctx, p_cd2);

    // 7. outputs[b,s] = dec_v . tanh(Wd1@st + cd2)
    pointer_kernel<false><<<dim3(SS / 128, BB), 256>>>(dec_W, 2 * HH, 0, st,
                                                       nullptr, p_cd2, dec_v, out);
}

// round 3
// speedup vs baseline: 1.0014x; 1.0003x over previous
#include <cuda_runtime.h>
#include <cstdint>

#define BB 256
#define HH 512
#define SS 512
#define H3 1536

// ---------------- scratch (no allocations allowed) ----------------
__device__ float g_hnew[BB * HH];
__device__ float g_hc[BB * HH];
__device__ float g_scores[BB * SS];
__device__ float g_attns[BB * SS];
__device__ float g_context[BB * HH];
__device__ float g_cd2[BB * HH];

// ---------------- f32x2 packed-FMA helpers (sm_103a FFMA2) ----------------
__device__ __forceinline__ unsigned long long dup_f32x2(float x) {
    unsigned long long r;
    unsigned u = __float_as_uint(x);
    asm("mov.b64 %0, {%1,%2};" : "=l"(r) : "r"(u), "r"(u));
    return r;
}
__device__ __forceinline__ void fma_f32x2(unsigned long long& d,
                                          unsigned long long a,
                                          unsigned long long b) {
    asm("fma.rn.f32x2 %0, %1, %2, %0;" : "+l"(d) : "l"(a), "l"(b));
}
__device__ __forceinline__ float2 unpack_f32x2(unsigned long long v) {
    unsigned lo, hi;
    asm("mov.b64 {%0,%1}, %2;" : "=r"(lo), "=r"(hi) : "l"(v));
    return make_float2(__uint_as_float(lo), __uint_as_float(hi));
}

// Accurate-enough tanh independent of fast-math flags (~1e-6 rel).
__device__ __forceinline__ float my_tanh(float x) {
    float ax = fabsf(x);
    float e = __expf(-2.0f * ax);           // MUFU.EX2 path, ~2 ulp
    float r = (1.0f - e) / (1.0f + e);
    return copysignf(r, x);
}
__device__ __forceinline__ float my_sigmoid(float x) {
    return 1.0f / (1.0f + __expf(-x));
}

// ---------------- kernel 1: embedding + GRU step ----------------
__global__ void gru_kernel(const float* __restrict__ last_output,
                           const float* __restrict__ last_hidden,
                           const float* __restrict__ emb_W,
                           const float* __restrict__ emb_b,
                           const float* __restrict__ Wih,
                           const float* __restrict__ Whh,
                           const float* __restrict__ bih,
                           const float* __restrict__ bhh,
                           float* __restrict__ hidden_out) {
    int b = blockIdx.x;
    int t = threadIdx.x;  // 256 threads
    __shared__ float sx[HH], sh[HH];
    __shared__ float sgx[H3], sgh[H3];

    float o0 = last_output[b * 2 + 0];
    float o1 = last_output[b * 2 + 1];
    for (int j = t; j < HH; j += 256) {
        sx[j] = o0 * emb_W[j * 2 + 0] + o1 * emb_W[j * 2 + 1] + emb_b[j];
        sh[j] = last_hidden[b * HH + j];
    }
    __syncthreads();

    for (int j = t; j < H3; j += 256) {
        float ax = bih[j], ah = bhh[j];
        const float4* wi = (const float4*)(Wih + (size_t)j * HH);
        const float4* wh = (const float4*)(Whh + (size_t)j * HH);
#pragma unroll 4
        for (int k4 = 0; k4 < HH / 4; k4++) {
            float4 a = wi[k4];
            float4 c = wh[k4];
            int k = k4 * 4;
            ax += a.x * sx[k] + a.y * sx[k + 1] + a.z * sx[k + 2] + a.w * sx[k + 3];
            ah += c.x * sh[k] + c.y * sh[k + 1] + c.z * sh[k + 2] + c.w * sh[k + 3];
        }
        sgx[j] = ax;
        sgh[j] = ah;
    }
    __syncthreads();

    for (int j = t; j < HH; j += 256) {
        float r = my_sigmoid(sgx[j] + sgh[j]);
        float z = my_sigmoid(sgx[HH + j] + sgh[HH + j]);
        float n = my_tanh(sgx[2 * HH + j] + r * sgh[2 * HH + j]);
        float hn = (1.0f - z) * n + z * sh[j];
        g_hnew[b * HH + j] = hn;
        hidden_out[b * HH + j] = hn;  // second output of reference
    }
}

// ---------------- kernel: out[b,h] = sum_k M[h, off+k] * vec[b,k] ----------------
__global__ void matvec_kernel(const float* __restrict__ M, int ldm, int off,
                              const float* __restrict__ vec,
                              float* __restrict__ out) {
    int b = blockIdx.y;
    int h0 = blockIdx.x * 64;
    int t = threadIdx.x;  // 256 threads, 4 per row
    __shared__ float sv[HH];
    for (int k = t; k < HH; k += 256) sv[k] = vec[b * HH + k];
    __syncthreads();

    int hl = t >> 2, l4 = t & 3;
    int h = h0 + hl;
    const float* m = M + (size_t)h * ldm + off;
    float acc = 0.0f;
    for (int k = l4 * 4; k < HH; k += 16) {
        float4 mv = *(const float4*)(m + k);
        acc += mv.x * sv[k] + mv.y * sv[k + 1] + mv.z * sv[k + 2] + mv.w * sv[k + 3];
    }
    acc += __shfl_xor_sync(0xffffffffu, acc, 1);
    acc += __shfl_xor_sync(0xffffffffu, acc, 2);
    if (l4 == 0) out[b * HH + h] = acc;
}

// ---------------- the big fused kernel ----------------
// out[b,s] = sum_h vvec[h] * tanh( (A1@X1)[h,s] (+ (A2@X2)[h,s]) + addvec[b,h] )
// A1 = A[:, 0:512], A2 = A[:, offB:offB+512] (row stride lda).
// X = [B,H,S] batched, contraction over H (k) for each (b,s) column.
template <bool DUAL>
__global__ __launch_bounds__(256, 2) void pointer_kernel(
    const float* __restrict__ A, int lda, int offB,
    const float* __restrict__ Xs, const float* __restrict__ Xd,
    const float* __restrict__ addvec, const float* __restrict__ vvec,
    float* __restrict__ outp) {
    int b = blockIdx.y;
    int s0 = blockIdx.x * 128;
    int t = threadIdx.x;
    int ty = t >> 4;   // 0..15 (rows)
    int tx = t & 15;   // 0..15 (cols)

    __shared__ __align__(16) float Aa[16][128];
    __shared__ __align__(16) float Ab[16][128];
    __shared__ __align__(16) float Bs[16][128];
    __shared__ __align__(16) float Bd[16][128];
    __shared__ float red[16][128];

    const float* Xsb = Xs + (size_t)b * HH * SS;
    const float* Xdb = DUAL ? (Xd + (size_t)b * HH * SS) : Xs;

    float p[8];
#pragma unroll
    for (int j = 0; j < 8; j++) p[j] = 0.0f;

    for (int hch = 0; hch < HH; hch += 128) {
        unsigned long long acc[8][4];
#pragma unroll
        for (int i = 0; i < 8; i++)
#pragma unroll
            for (int j = 0; j < 4; j++) acc[i][j] = 0ull;

        for (int k0 = 0; k0 < HH; k0 += 16) {
            // A tiles, stored transposed: Aa[k][h]
#pragma unroll
            for (int r = 0; r < 2; r++) {
                int id = t + r * 256;      // 0..511
                int h = id >> 2;           // 0..127
                int q = id & 3;            // k-quad
                const float* ap = A + (size_t)(hch + h) * lda + k0 + q * 4;
                float4 a4 = *(const float4*)ap;
                Aa[q * 4 + 0][h] = a4.x;
                Aa[q * 4 + 1][h] = a4.y;
                Aa[q * 4 + 2][h] = a4.z;
                Aa[q * 4 + 3][h] = a4.w;
                if (DUAL) {
                    float4 c4 = *(const float4*)(ap + offB);
                    Ab[q * 4 + 0][h] = c4.x;
                    Ab[q * 4 + 1][h] = c4.y;
                    Ab[q * 4 + 2][h] = c4.z;
                    Ab[q * 4 + 3][h] = c4.w;
                }
            }
            // B tiles: Bs[k][s]
#pragma unroll
            for (int r = 0; r < 2; r++) {
                int id = t + r * 256;  // 0..511
                int k = id >> 5;       // 0..15
                int m = id & 31;       // quad within the 128-col row
                *(float4*)&Bs[k][m * 4] =
                    *(const float4*)(Xsb + (size_t)(k0 + k) * SS + s0 + m * 4);
                if (DUAL)
                    *(float4*)&Bd[k][m * 4] =
                        *(const float4*)(Xdb + (size_t)(k0 + k) * SS + s0 + m * 4);
            }
            __syncthreads();

#pragma unroll
            for (int kk = 0; kk < 16; kk++) {
                float4 a0 = *(const float4*)&Aa[kk][ty * 8];
                float4 a1 = *(const float4*)&Aa[kk][ty * 8 + 4];
                ulonglong2 bs0 = *(const ulonglong2*)&Bs[kk][tx * 8];
                ulonglong2 bs1 = *(const ulonglong2*)&Bs[kk][tx * 8 + 4];
                float ar[8] = {a0.x, a0.y, a0.z, a0.w, a1.x, a1.y, a1.z, a1.w};
#pragma unroll
                for (int i = 0; i < 8; i++) {
                    unsigned long long ad = dup_f32x2(ar[i]);
                    fma_f32x2(acc[i][0], ad, bs0.x);
                    fma_f32x2(acc[i][1], ad, bs0.y);
                    fma_f32x2(acc[i][2], ad, bs1.x);
                    fma_f32x2(acc[i][3], ad, bs1.y);
                }
                if (DUAL) {
                    float4 c0 = *(const float4*)&Ab[kk][ty * 8];
                    float4 c1 = *(const float4*)&Ab[kk][ty * 8 + 4];
                    ulonglong2 bd0 = *(const ulonglong2*)&Bd[kk][tx * 8];
                    ulonglong2 bd1 = *(const ulonglong2*)&Bd[kk][tx * 8 + 4];
                    float ar2[8] = {c0.x, c0.y, c0.z, c0.w, c1.x, c1.y, c1.z, c1.w};
#pragma unroll
                    for (int i = 0; i < 8; i++) {
                        unsigned long long ad = dup_f32x2(ar2[i]);
                        fma_f32x2(acc[i][0], ad, bd0.x);
                        fma_f32x2(acc[i][1], ad, bd0.y);
                        fma_f32x2(acc[i][2], ad, bd1.x);
                        fma_f32x2(acc[i][3], ad, bd1.y);
                    }
                }
            }
            __syncthreads();
        }

        // epilogue for this h-chunk: add bias, tanh, weight by vvec, fold into p
#pragma unroll
        for (int i = 0; i < 8; i++) {
            int h = hch + ty * 8 + i;
            float av = addvec[b * HH + h];
            float vv = vvec[h];
#pragma unroll
            for (int jp = 0; jp < 4; jp++) {
                float2 c = unpack_f32x2(acc[i][jp]);
                p[2 * jp + 0] += vv * my_tanh(c.x + av);
                p[2 * jp + 1] += vv * my_tanh(c.y + av);
            }
        }
    }

    // reduce partial sums over ty (16-way) in smem
#pragma unroll
    for (int j = 0; j < 8; j++) red[ty][tx * 8 + j] = p[j];
    __syncthreads();
    for (int off = 8; off > 0; off >>= 1) {
        if (ty < off) {
#pragma unroll
            for (int j = 0; j < 8; j++)
                red[ty][tx * 8 + j] += red[ty + off][tx * 8 + j];
        }
        __syncthreads();
    }
    if (ty == 0) {
#pragma unroll
        for (int j = 0; j < 8; j++)
            outp[b * SS + s0 + tx * 8 + j] = red[0][tx * 8 + j];
    }
}

// ---------------- softmax over S per batch row ----------------
__global__ void softmax_kernel(const float* __restrict__ scores,
                               float* __restrict__ attns) {
    int b = blockIdx.x;
    int t = threadIdx.x;  // 256
    __shared__ float sm[256];
    float v0 = scores[b * SS + t];
    float v1 = scores[b * SS + 256 + t];
    sm[t] = fmaxf(v0, v1);
    __syncthreads();
    for (int off = 128; off > 0; off >>= 1) {
        if (t < off) sm[t] = fmaxf(sm[t], sm[t + off]);
        __syncthreads();
    }
    float mx = sm[0];
    __syncthreads();
    float e0 = __expf(v0 - mx);
    float e1 = __expf(v1 - mx);
    sm[t] = e0 + e1;
    __syncthreads();
    for (int off = 128; off > 0; off >>= 1) {
        if (t < off) sm[t] += sm[t + off];
        __syncthreads();
    }
    float inv = 1.0f / sm[0];
    attns[b * SS + t] = e0 * inv;
    attns[b * SS + 256 + t] = e1 * inv;
}

// ---------------- context[b,h] = sum_s attns[b,s] * static[b,h,s] ----------------
__global__ void context_kernel(const float* __restrict__ st,
                               const float* __restrict__ attns,
                               float* __restrict__ ctx) {
    int b = blockIdx.y;
    int h0 = blockIdx.x * 8;
    int w = threadIdx.x >> 5, l = threadIdx.x & 31;
    __shared__ float sa[SS];
    for (int s = threadIdx.x; s < SS; s += 256) sa[s] = attns[b * SS + s];
    __syncthreads();
    int h = h0 + w;
    const float* row = st + (size_t)b * HH * SS + (size_t)h * SS;
    float acc = 0.0f;
    for (int s = l * 4; s < SS; s += 128) {
        float4 r4 = *(const float4*)(row + s);
        acc += r4.x * sa[s] + r4.y * sa[s + 1] + r4.z * sa[s + 2] + r4.w * sa[s + 3];
    }
#pragma unroll
    for (int off = 16; off > 0; off >>= 1)
        acc += __shfl_xor_sync(0xffffffffu, acc, off);
    if (l == 0) ctx[b * HH + h] = acc;
}

// ---------------- launch ----------------
extern "C" void kernel_launch(void* const* d_in, const int* in_sizes, int n_in,
                              void* d_out, int out_size) {
    const float* st     = (const float*)d_in[0];
    const float* dy     = (const float*)d_in[1];
    const float* lo     = (const float*)d_in[2];
    const float* lh     = (const float*)d_in[3];
    const float* embW   = (const float*)d_in[4];
    const float* embb   = (const float*)d_in[5];
    const float* Wih    = (const float*)d_in[6];
    const float* Whh    = (const float*)d_in[7];
    const float* bih    = (const float*)d_in[8];
    const float* bhh    = (const float*)d_in[9];
    const float* attn_v = (const float*)d_in[10];
    const float* attn_W = (const float*)d_in[11];
    const float* dec_v  = (const float*)d_in[12];
    const float* dec_W  = (const float*)d_in[13];
    float* out = (float*)d_out;  // [B*S] outputs, then [B*H] hidden

    float *p_hnew, *p_hc, *p_scores, *p_attns, *p_ctx, *p_cd2;
    cudaGetSymbolAddress((void**)&p_hnew, g_hnew);
    cudaGetSymbolAddress((void**)&p_hc, g_hc);
    cudaGetSymbolAddress((void**)&p_scores, g_scores);
    cudaGetSymbolAddress((void**)&p_attns, g_attns);
    cudaGetSymbolAddress((void**)&p_ctx, g_context);
    cudaGetSymbolAddress((void**)&p_cd2, g_cd2);

    // 1. embedding + GRU -> h_new (also writes hidden output)
    gru_kernel<<<BB, 256>>>(lo, lh, embW, embb, Wih, Whh, bih, bhh, out + BB * SS);

    // 2. hc[b,h] = h_new @ Wc^T  (Wc = attn_W[:, 2H:3H])
    matvec_kernel<<<dim3(8, BB), 256>>>(attn_W, H3, 2 * HH, p_hnew, p_hc);

    // 3. scores[b,s] = v . tanh(Wa@st + Wb@dy + hc)
    pointer_kernel<true><<<dim3(SS / 128, BB), 256>>>(attn_W, H3, HH, st, dy,
                                                      p_hc, attn_v, p_scores);

    // 4. softmax over s
    softmax_kernel<<<BB, 256>>>(p_scores, p_attns);

    // 5. context
    context_kernel<<<dim3(HH / 8, BB), 256>>>(st, p_attns, p_ctx);

    // 6. cd2[b,h] = context @ Wd2^T (Wd2 = dec_W[:, H:2H])
    matvec_kernel<<<dim3(8, BB), 256>>>(dec_W, 2 * HH, HH, p_ctx, p_cd2);

    // 7. outputs[b,s] = dec_v . tanh(Wd1@st + cd2)
    pointer_kernel<false><<<dim3(SS / 128, BB), 256>>>(dec_W, 2 * HH, 0, st,
                                                       nullptr, p_cd2, dec_v, out);
}

// round 5
// speedup vs baseline: 1.2561x; 1.2543x over previous
#include <cuda_runtime.h>
#include <cstdint>

#define BB 256
#define HH 512
#define SS 512
#define H3 1536

// ---------------- scratch ----------------
__device__ float g_hnew[BB * HH];
__device__ float g_hc[BB * HH];
__device__ float g_scores[BB * SS];
__device__ float g_attns[BB * SS];
__device__ float g_context[BB * HH];
__device__ float g_cd2[BB * HH];

// ---------------- math ----------------
__device__ __forceinline__ float my_tanh(float x) {
    float ax = fabsf(x);
    float e = __expf(-2.0f * ax);
    float r = __fdividef(1.0f - e, 1.0f + e);
    return copysignf(r, x);
}
__device__ __forceinline__ float my_sigmoid(float x) {
    return 1.0f / (1.0f + __expf(-x));
}

// ---------------- tf32 helpers ----------------
__device__ __forceinline__ void split_tf32(float x, uint32_t& hi, uint32_t& lo) {
    asm("cvt.rna.tf32.f32 %0, %1;" : "=r"(hi) : "f"(x));
    float r = x - __uint_as_float(hi);
    asm("cvt.rna.tf32.f32 %0, %1;" : "=r"(lo) : "f"(r));
}
__device__ __forceinline__ void mma_tf32(float* d, const uint32_t* a, const uint32_t* b) {
    asm volatile(
        "mma.sync.aligned.m16n8k8.row.col.f32.tf32.tf32.f32 "
        "{%0,%1,%2,%3}, {%4,%5,%6,%7}, {%8,%9}, {%0,%1,%2,%3};"
        : "+f"(d[0]), "+f"(d[1]), "+f"(d[2]), "+f"(d[3])
        : "r"(a[0]), "r"(a[1]), "r"(a[2]), "r"(a[3]), "r"(b[0]), "r"(b[1]));
}
__device__ __forceinline__ uint32_t smem_u32(const void* p) {
    uint32_t a;
    asm("{ .reg .u64 t; cvta.to.shared.u64 t, %1; cvt.u32.u64 %0, t; }" : "=r"(a) : "l"(p));
    return a;
}
__device__ __forceinline__ void cp16(uint32_t dst, const void* src) {
    asm volatile("cp.async.cg.shared.global [%0], [%1], 16;" :: "r"(dst), "l"(src));
}
#define CP_COMMIT() asm volatile("cp.async.commit_group;" ::: "memory")
#define CP_WAIT(n)  asm volatile("cp.async.wait_group %0;" :: "n"(n) : "memory")

// ---------------- tile config ----------------
#define TK 32
#define A_STRIDE 36    /* floats per A smem row (32 + 4 pad) */
#define B_STRIDE 136   /* floats per B smem row (128 + 8 pad) */
#define A_FLOATS (128 * A_STRIDE)          /* 4608 */
#define B_FLOATS (TK * B_STRIDE)           /* 4352 */
#define STAGE_FLOATS (A_FLOATS + B_FLOATS) /* 8960 */
#define SMEM_FLOATS (2 * STAGE_FLOATS + 256)
#define SMEM_BYTES (SMEM_FLOATS * 4)       /* 72704 */

// ============================================================================
// Fused GEMM + v.tanh(.) reduce:
//   outp[b, n0+c] = sum_h vvec[h] * tanh( sum_k A[h,k]*X(k)[k%512, c] + addvec[b,h] )
// KSEG=2: K=1024, X = st for k<512, dy for k>=512 (A cols 0..1023 = [Wa|Wb]).
// KSEG=1: K=512,  X = st.
// Grid: (4 n-tiles, BB). CTA loops m-tiles internally -> deterministic store.
// ============================================================================
template <int KSEG>
__global__ __launch_bounds__(256, 1) void gemm_tf32_kernel(
    const float* __restrict__ A, int lda,
    const float* __restrict__ X1, const float* __restrict__ X2,
    const float* __restrict__ addvec, const float* __restrict__ vvec,
    float* __restrict__ outp) {
    extern __shared__ float sm[];
    float* colacc = sm + 2 * STAGE_FLOATS;
    const uint32_t smb = smem_u32(sm);

    const int tid = threadIdx.x;
    const int lane = tid & 31;
    const int wid = tid >> 5;
    const int wm = wid >> 2;        // 0..1 (64 m each)
    const int wn = wid & 3;         // 0..3 (32 n each)
    const int gid = lane >> 2;      // 0..7
    const int lt4 = lane & 3;       // 0..3
    const int n0 = blockIdx.x * 128;
    const int b = blockIdx.y;

    if (tid < 256) colacc[tid] = 0.0f;
    __syncthreads();

    const int NCH = KSEG * 16;  // K / TK

#pragma unroll 1
    for (int mt = 0; mt < 4; mt++) {
        float acc[4][4][4];
#pragma unroll
        for (int i = 0; i < 4; i++)
#pragma unroll
            for (int j = 0; j < 4; j++)
#pragma unroll
                for (int q = 0; q < 4; q++) acc[i][j][q] = 0.0f;

        // ---- chunk issue lambda (manually inlined twice) ----
        // A granules: 128 rows x 8 (16B); B granules: 32 rows x 32.
#define ISSUE_CHUNK(CH, STG) do { \
        int _kg = (CH) * TK; \
        const float* _X = (KSEG == 2 && _kg >= 512) ? X2 : X1; \
        int _kk = _kg & 511; \
        uint32_t _as = smb + (STG) * STAGE_FLOATS * 4; \
        uint32_t _bs = _as + A_FLOATS * 4; \
        _Pragma("unroll") \
        for (int _i = 0; _i < 4; _i++) { \
            int _gi = _i * 256 + tid; \
            int _row = _gi >> 3, _g = _gi & 7; \
            cp16(_as + (_row * A_STRIDE + _g * 4) * 4, \
                 A + (size_t)(mt * 128 + _row) * lda + _kg + _g * 4); \
        } \
        _Pragma("unroll") \
        for (int _i = 0; _i < 4; _i++) { \
            int _gi = _i * 256 + tid; \
            int _k = _gi >> 5, _g = _gi & 31; \
            cp16(_bs + (_k * B_STRIDE + _g * 4) * 4, \
                 _X + ((size_t)b * HH + _kk + _k) * SS + n0 + _g * 4); \
        } \
        CP_COMMIT(); \
    } while (0)

        ISSUE_CHUNK(0, 0);

#pragma unroll 1
        for (int ch = 0; ch < NCH; ch++) {
            if (ch + 1 < NCH) ISSUE_CHUNK(ch + 1, (ch + 1) & 1);
            if (ch + 1 < NCH) CP_WAIT(1); else CP_WAIT(0);
            __syncthreads();

            const float* As = sm + (ch & 1) * STAGE_FLOATS;
            const float* Bs = As + A_FLOATS;

#pragma unroll
            for (int ks = 0; ks < 4; ks++) {
                uint32_t ah[4][4], al[4][4], bh[4][2], bl[4][2];
#pragma unroll
                for (int mf = 0; mf < 4; mf++) {
                    int rb = (wm * 64 + mf * 16 + gid) * A_STRIDE + ks * 8 + lt4;
                    split_tf32(As[rb],                    ah[mf][0], al[mf][0]);
                    split_tf32(As[rb + 8 * A_STRIDE],     ah[mf][1], al[mf][1]);
                    split_tf32(As[rb + 4],                ah[mf][2], al[mf][2]);
                    split_tf32(As[rb + 8 * A_STRIDE + 4], ah[mf][3], al[mf][3]);
                }
#pragma unroll
                for (int nf = 0; nf < 4; nf++) {
                    int cb = (ks * 8 + lt4) * B_STRIDE + wn * 32 + nf * 8 + gid;
                    split_tf32(Bs[cb],                bh[nf][0], bl[nf][0]);
                    split_tf32(Bs[cb + 4 * B_STRIDE], bh[nf][1], bl[nf][1]);
                }
                // 3 split terms, 16-instruction reuse distance per accumulator
#pragma unroll
                for (int mf = 0; mf < 4; mf++)
#pragma unroll
                    for (int nf = 0; nf < 4; nf++)
                        mma_tf32(acc[mf][nf], ah[mf], bh[nf]);
#pragma unroll
                for (int mf = 0; mf < 4; mf++)
#pragma unroll
                    for (int nf = 0; nf < 4; nf++)
                        mma_tf32(acc[mf][nf], ah[mf], bl[nf]);
#pragma unroll
                for (int mf = 0; mf < 4; mf++)
#pragma unroll
                    for (int nf = 0; nf < 4; nf++)
                        mma_tf32(acc[mf][nf], al[mf], bh[nf]);
            }
            __syncthreads();
        }

        // ---- epilogue for this m-tile ----
        float p0[4], p1[4];
#pragma unroll
        for (int nf = 0; nf < 4; nf++) { p0[nf] = 0.0f; p1[nf] = 0.0f; }
#pragma unroll
        for (int mf = 0; mf < 4; mf++) {
            int h0 = mt * 128 + wm * 64 + mf * 16 + gid;
            float vv0 = vvec[h0], vv1 = vvec[h0 + 8];
            float av0 = addvec[b * HH + h0], av1 = addvec[b * HH + h0 + 8];
#pragma unroll
            for (int nf = 0; nf < 4; nf++) {
                p0[nf] += vv0 * my_tanh(acc[mf][nf][0] + av0)
                        + vv1 * my_tanh(acc[mf][nf][2] + av1);
                p1[nf] += vv0 * my_tanh(acc[mf][nf][1] + av0)
                        + vv1 * my_tanh(acc[mf][nf][3] + av1);
            }
        }
#pragma unroll
        for (int nf = 0; nf < 4; nf++) {
            float a0 = p0[nf], a1 = p1[nf];
#pragma unroll
            for (int d = 4; d < 32; d <<= 1) {
                a0 += __shfl_xor_sync(0xffffffffu, a0, d);
                a1 += __shfl_xor_sync(0xffffffffu, a1, d);
            }
            if (gid == 0) {
                int c = wm * 128 + wn * 32 + nf * 8 + lt4 * 2;
                colacc[c] += a0;
                colacc[c + 1] += a1;
            }
        }
        __syncthreads();
    }

    if (tid < 128) outp[(size_t)b * SS + n0 + tid] = colacc[tid] + colacc[128 + tid];
#undef ISSUE_CHUNK
}

// ---------------- GRU ----------------
__global__ void gru_kernel(const float* __restrict__ last_output,
                           const float* __restrict__ last_hidden,
                           const float* __restrict__ emb_W,
                           const float* __restrict__ emb_b,
                           const float* __restrict__ Wih,
                           const float* __restrict__ Whh,
                           const float* __restrict__ bih,
                           const float* __restrict__ bhh,
                           float* __restrict__ hidden_out) {
    int b = blockIdx.x;
    int t = threadIdx.x;
    __shared__ float sx[HH], sh[HH];
    __shared__ float sgx[H3], sgh[H3];
    float o0 = last_output[b * 2 + 0];
    float o1 = last_output[b * 2 + 1];
    for (int j = t; j < HH; j += 256) {
        sx[j] = o0 * emb_W[j * 2 + 0] + o1 * emb_W[j * 2 + 1] + emb_b[j];
        sh[j] = last_hidden[b * HH + j];
    }
    __syncthreads();
    for (int j = t; j < H3; j += 256) {
        float ax = bih[j], ah = bhh[j];
        const float4* wi = (const float4*)(Wih + (size_t)j * HH);
        const float4* wh = (const float4*)(Whh + (size_t)j * HH);
#pragma unroll 4
        for (int k4 = 0; k4 < HH / 4; k4++) {
            float4 a = wi[k4];
            float4 c = wh[k4];
            int k = k4 * 4;
            ax += a.x * sx[k] + a.y * sx[k + 1] + a.z * sx[k + 2] + a.w * sx[k + 3];
            ah += c.x * sh[k] + c.y * sh[k + 1] + c.z * sh[k + 2] + c.w * sh[k + 3];
        }
        sgx[j] = ax;
        sgh[j] = ah;
    }
    __syncthreads();
    for (int j = t; j < HH; j += 256) {
        float r = my_sigmoid(sgx[j] + sgh[j]);
        float z = my_sigmoid(sgx[HH + j] + sgh[HH + j]);
        float n = my_tanh(sgx[2 * HH + j] + r * sgh[2 * HH + j]);
        float hn = (1.0f - z) * n + z * sh[j];
        g_hnew[b * HH + j] = hn;
        hidden_out[b * HH + j] = hn;
    }
}

// ---------------- matvec ----------------
__global__ void matvec_kernel(const float* __restrict__ M, int ldm, int off,
                              const float* __restrict__ vec,
                              float* __restrict__ out) {
    int b = blockIdx.y;
    int h0 = blockIdx.x * 64;
    int t = threadIdx.x;
    __shared__ float sv[HH];
    for (int k = t; k < HH; k += 256) sv[k] = vec[b * HH + k];
    __syncthreads();
    int hl = t >> 2, l4 = t & 3;
    int h = h0 + hl;
    const float* m = M + (size_t)h * ldm + off;
    float acc = 0.0f;
    for (int k = l4 * 4; k < HH; k += 16) {
        float4 mv = *(const float4*)(m + k);
        acc += mv.x * sv[k] + mv.y * sv[k + 1] + mv.z * sv[k + 2] + mv.w * sv[k + 3];
    }
    acc += __shfl_xor_sync(0xffffffffu, acc, 1);
    acc += __shfl_xor_sync(0xffffffffu, acc, 2);
    if (l4 == 0) out[b * HH + h] = acc;
}

// ---------------- softmax ----------------
__global__ void softmax_kernel(const float* __restrict__ scores,
                               float* __restrict__ attns) {
    int b = blockIdx.x;
    int t = threadIdx.x;
    __shared__ float sm[256];
    float v0 = scores[b * SS + t];
    float v1 = scores[b * SS + 256 + t];
    sm[t] = fmaxf(v0, v1);
    __syncthreads();
    for (int off = 128; off > 0; off >>= 1) {
        if (t < off) sm[t] = fmaxf(sm[t], sm[t + off]);
        __syncthreads();
    }
    float mx = sm[0];
    __syncthreads();
    float e0 = __expf(v0 - mx);
    float e1 = __expf(v1 - mx);
    sm[t] = e0 + e1;
    __syncthreads();
    for (int off = 128; off > 0; off >>= 1) {
        if (t < off) sm[t] += sm[t + off];
        __syncthreads();
    }
    float inv = 1.0f / sm[0];
    attns[b * SS + t] = e0 * inv;
    attns[b * SS + 256 + t] = e1 * inv;
}

// ---------------- context ----------------
__global__ void context_kernel(const float* __restrict__ st,
                               const float* __restrict__ attns,
                               float* __restrict__ ctx) {
    int b = blockIdx.y;
    int h0 = blockIdx.x * 8;
    int w = threadIdx.x >> 5, l = threadIdx.x & 31;
    __shared__ float sa[SS];
    for (int s = threadIdx.x; s < SS; s += 256) sa[s] = attns[b * SS + s];
    __syncthreads();
    int h = h0 + w;
    const float* row = st + (size_t)b * HH * SS + (size_t)h * SS;
    float acc = 0.0f;
    for (int s = l * 4; s < SS; s += 128) {
        float4 r4 = *(const float4*)(row + s);
        acc += r4.x * sa[s] + r4.y * sa[s + 1] + r4.z * sa[s + 2] + r4.w * sa[s + 3];
    }
#pragma unroll
    for (int off = 16; off > 0; off >>= 1)
        acc += __shfl_xor_sync(0xffffffffu, acc, off);
    if (l == 0) ctx[b * HH + h] = acc;
}

// ---------------- launch ----------------
extern "C" void kernel_launch(void* const* d_in, const int* in_sizes, int n_in,
                              void* d_out, int out_size) {
    const float* st     = (const float*)d_in[0];
    const float* dy     = (const float*)d_in[1];
    const float* lo     = (const float*)d_in[2];
    const float* lh     = (const float*)d_in[3];
    const float* embW   = (const float*)d_in[4];
    const float* embb   = (const float*)d_in[5];
    const float* Wih    = (const float*)d_in[6];
    const float* Whh    = (const float*)d_in[7];
    const float* bih    = (const float*)d_in[8];
    const float* bhh    = (const float*)d_in[9];
    const float* attn_v = (const float*)d_in[10];
    const float* attn_W = (const float*)d_in[11];
    const float* dec_v  = (const float*)d_in[12];
    const float* dec_W  = (const float*)d_in[13];
    float* out = (float*)d_out;

    float *p_hnew, *p_hc, *p_scores, *p_attns, *p_ctx, *p_cd2;
    cudaGetSymbolAddress((void**)&p_hnew, g_hnew);
    cudaGetSymbolAddress((void**)&p_hc, g_hc);
    cudaGetSymbolAddress((void**)&p_scores, g_scores);
    cudaGetSymbolAddress((void**)&p_attns, g_attns);
    cudaGetSymbolAddress((void**)&p_ctx, g_context);
    cudaGetSymbolAddress((void**)&p_cd2, g_cd2);

    cudaFuncSetAttribute(gemm_tf32_kernel<2>,
                         cudaFuncAttributeMaxDynamicSharedMemorySize, SMEM_BYTES);
    cudaFuncSetAttribute(gemm_tf32_kernel<1>,
                         cudaFuncAttributeMaxDynamicSharedMemorySize, SMEM_BYTES);

    // 1. embedding + GRU -> h_new (also writes hidden output)
    gru_kernel<<<BB, 256>>>(lo, lh, embW, embb, Wih, Whh, bih, bhh, out + BB * SS);

    // 2. hc[b,h] = h_new @ Wc^T  (Wc = attn_W[:, 2H:3H])
    matvec_kernel<<<dim3(8, BB), 256>>>(attn_W, H3, 2 * HH, p_hnew, p_hc);

    // 3. scores[b,s] = attn_v . tanh(Wa@st + Wb@dy + hc)   (K=1024 fused)
    gemm_tf32_kernel<2><<<dim3(4, BB), 256, SMEM_BYTES>>>(
        attn_W, H3, st, dy, p_hc, attn_v, p_scores);

    // 4. softmax
    softmax_kernel<<<BB, 256>>>(p_scores, p_attns);

    // 5. context
    context_kernel<<<dim3(HH / 8, BB), 256>>>(st, p_attns, p_ctx);

    // 6. cd2[b,h] = context @ Wd2^T (Wd2 = dec_W[:, H:2H])
    matvec_kernel<<<dim3(8, BB), 256>>>(dec_W, 2 * HH, HH, p_ctx, p_cd2);

    // 7. outputs[b,s] = dec_v . tanh(Wd1@st + cd2)
    gemm_tf32_kernel<1><<<dim3(4, BB), 256, SMEM_BYTES>>>(
        dec_W, 2 * HH, st, nullptr, p_cd2, dec_v, out);
}

// round 6
// speedup vs baseline: 2.1823x; 1.7374x over previous
#include <cuda_runtime.h>
#include <cuda_bf16.h>
#include <cstdint>

#define BB 256
#define HH 512
#define SS 512
#define H3 1536

// ---------------- scratch ----------------
__device__ float g_hnew[BB * HH];
__device__ float g_hc[BB * HH];
__device__ float g_scores[BB * SS];
__device__ float g_attns[BB * SS];
__device__ float g_context[BB * HH];
__device__ float g_cd2[BB * HH];

// pre-split bf16 operands
__device__ __nv_bfloat16 g_st_hi[BB * HH * SS];
__device__ __nv_bfloat16 g_st_lo[BB * HH * SS];
__device__ __nv_bfloat16 g_dy_hi[BB * HH * SS];
__device__ __nv_bfloat16 g_dy_lo[BB * HH * SS];
__device__ __nv_bfloat16 g_Wab_hi[HH * 1024], g_Wab_lo[HH * 1024];
__device__ __nv_bfloat16 g_Wd_hi[HH * HH],    g_Wd_lo[HH * HH];

// ---------------- math ----------------
__device__ __forceinline__ float my_tanh(float x) {
    float ax = fabsf(x);
    float e = __expf(-2.0f * ax);
    float r = __fdividef(1.0f - e, 1.0f + e);
    return copysignf(r, x);
}
__device__ __forceinline__ float my_sigmoid(float x) {
    return 1.0f / (1.0f + __expf(-x));
}

// ---------------- PTX helpers ----------------
__device__ __forceinline__ uint32_t smem_u32(const void* p) {
    uint32_t a;
    asm("{ .reg .u64 t; cvta.to.shared.u64 t, %1; cvt.u32.u64 %0, t; }" : "=r"(a) : "l"(p));
    return a;
}
__device__ __forceinline__ void cp16(uint32_t dst, const void* src) {
    asm volatile("cp.async.cg.shared.global [%0], [%1], 16;" :: "r"(dst), "l"(src));
}
#define CP_COMMIT() asm volatile("cp.async.commit_group;" ::: "memory")
#define CP_WAIT(n)  asm volatile("cp.async.wait_group %0;" :: "n"(n) : "memory")

__device__ __forceinline__ void ldm_x4(uint32_t* r, uint32_t a) {
    asm volatile("ldmatrix.sync.aligned.m8n8.x4.shared.b16 {%0,%1,%2,%3}, [%4];"
        : "=r"(r[0]), "=r"(r[1]), "=r"(r[2]), "=r"(r[3]) : "r"(a));
}
__device__ __forceinline__ void ldm_x2t(uint32_t* r, uint32_t a) {
    asm volatile("ldmatrix.sync.aligned.m8n8.x2.trans.shared.b16 {%0,%1}, [%2];"
        : "=r"(r[0]), "=r"(r[1]) : "r"(a));
}
__device__ __forceinline__ void mma_bf16(float* d, const uint32_t* a, const uint32_t* b) {
    asm volatile(
        "mma.sync.aligned.m16n8k16.row.col.f32.bf16.bf16.f32 "
        "{%0,%1,%2,%3}, {%4,%5,%6,%7}, {%8,%9}, {%0,%1,%2,%3};"
        : "+f"(d[0]), "+f"(d[1]), "+f"(d[2]), "+f"(d[3])
        : "r"(a[0]), "r"(a[1]), "r"(a[2]), "r"(a[3]), "r"(b[0]), "r"(b[1]));
}

// ---------------- tile config (units: bf16 halves) ----------------
#define TK 32
#define A_SH 40            /* A smem row stride: 32 + 8 pad  */
#define B_SH 136           /* B smem row stride: 128 + 8 pad */
#define A_HALVES (128 * A_SH)           /* 5120 */
#define B_HALVES (TK * B_SH)            /* 4352 */
#define AL_OFF A_HALVES                  /* 5120  */
#define BH_OFF (2 * A_HALVES)            /* 10240 */
#define BL_OFF (2 * A_HALVES + B_HALVES) /* 14592 */
#define STAGE_HALVES (2 * A_HALVES + 2 * B_HALVES) /* 18944 */
#define SMEM_BYTES (2 * STAGE_HALVES * 2 + 256 * 4) /* 76800 */

// ---------------- prep kernels ----------------
__global__ void prep_w(const float* __restrict__ attn_W,
                       const float* __restrict__ dec_W) {
    int t = blockIdx.x * blockDim.x + threadIdx.x;  // 768*256 = 196608
#pragma unroll
    for (int i = 0; i < 4; i++) {
        int id = t + i * 196608;  // 0..786431
        float x;
        __nv_bfloat16 *dh, *dl;
        int e;
        if (id < 524288) {  // [Wa|Wb]: 512 x 1024
            int h = id >> 10, k = id & 1023;
            x = attn_W[h * H3 + k];
            dh = g_Wab_hi; dl = g_Wab_lo; e = id;
        } else {            // Wd1: 512 x 512
            e = id - 524288;
            int h = e >> 9, k = e & 511;
            x = dec_W[h * 1024 + k];
            dh = g_Wd_hi; dl = g_Wd_lo;
        }
        __nv_bfloat16 hi = __float2bfloat16(x);
        dh[e] = hi;
        dl[e] = __float2bfloat16(x - __bfloat162float(hi));
    }
}

__global__ void prep_enc(const float* __restrict__ st,
                         const float* __restrict__ dy) {
    size_t nth = (size_t)gridDim.x * blockDim.x;
    const size_t NG = 2ull * 16777216ull;  // float4 groups across both tensors
    for (size_t g = (size_t)blockIdx.x * blockDim.x + threadIdx.x; g < NG; g += nth) {
        bool isdy = g >= 16777216ull;
        const float* src = isdy ? dy : st;
        __nv_bfloat16* dh = isdy ? g_dy_hi : g_st_hi;
        __nv_bfloat16* dl = isdy ? g_dy_lo : g_st_lo;
        size_t off = (g & 16777215ull) * 4;
        float4 v = *(const float4*)(src + off);
        __nv_bfloat162 h01 = __floats2bfloat162_rn(v.x, v.y);
        __nv_bfloat162 h23 = __floats2bfloat162_rn(v.z, v.w);
        float2 f01 = __bfloat1622float2(h01);
        float2 f23 = __bfloat1622float2(h23);
        __nv_bfloat162 l01 = __floats2bfloat162_rn(v.x - f01.x, v.y - f01.y);
        __nv_bfloat162 l23 = __floats2bfloat162_rn(v.z - f23.x, v.w - f23.y);
        uint2 uh, ul;
        uh.x = *reinterpret_cast<unsigned*>(&h01);
        uh.y = *reinterpret_cast<unsigned*>(&h23);
        ul.x = *reinterpret_cast<unsigned*>(&l01);
        ul.y = *reinterpret_cast<unsigned*>(&l23);
        *(uint2*)(dh + off) = uh;
        *(uint2*)(dl + off) = ul;
    }
}

// ============================================================================
// bf16 HMMA GEMM + fused v.tanh(.) reduce.
//   outp[b, n0+c] = sum_h vvec[h] * tanh( sum_k W[h,k]*X(k)[k%512, n0+c] + addvec[b,h] )
// KSEG=2: K=1024, X = st (k<512) then dy. KSEG=1: K=512, X = st.
// Grid (4 n-tiles, BB); CTA loops 4 m-tiles; 8 warps, warp tile 64m x 32n.
// 3-term split precision: W = Whi+Wlo, X = Xhi+Xlo; D ~= hh + hl + lh.
// ============================================================================
template <int KSEG>
__global__ __launch_bounds__(256, 2) void gemm_bf16_kernel(
    const __nv_bfloat16* __restrict__ Whi, const __nv_bfloat16* __restrict__ Wlo,
    int lda,
    const __nv_bfloat16* __restrict__ st_hi, const __nv_bfloat16* __restrict__ st_lo,
    const __nv_bfloat16* __restrict__ dy_hi, const __nv_bfloat16* __restrict__ dy_lo,
    const float* __restrict__ addvec, const float* __restrict__ vvec,
    float* __restrict__ outp) {
    extern __shared__ char smch[];
    const uint32_t smb = smem_u32(smch);
    float* colacc = (float*)(smch + 2 * STAGE_HALVES * 2);

    const int tid = threadIdx.x;
    const int lane = tid & 31;
    const int wid = tid >> 5;
    const int wm = wid >> 2;   // 0..1
    const int wn = wid & 3;    // 0..3
    const int gid = lane >> 2; // 0..7
    const int lt4 = lane & 3;  // 0..3
    const int n0 = blockIdx.x * 128;
    const int b = blockIdx.y;

    if (tid < 256) colacc[tid] = 0.0f;
    __syncthreads();

    const int NCH = KSEG * 16;

    // fragment base addresses (lane-dependent, stage-relative, bytes)
    const uint32_t a_lane = ((wm * 64 + (lane & 15)) * A_SH + (lane >> 4) * 8) * 2;
    const uint32_t b_lane = (BH_OFF + (lane & 15) * B_SH + wn * 32) * 2;

#pragma unroll 1
    for (int mt = 0; mt < 4; mt++) {
        float acc[4][4][4];
#pragma unroll
        for (int i = 0; i < 4; i++)
#pragma unroll
            for (int j = 0; j < 4; j++)
#pragma unroll
                for (int q = 0; q < 4; q++) acc[i][j][q] = 0.0f;

#define ISSUE_CHUNK(CH, STG) do { \
        int _kg = (CH) * TK; \
        const __nv_bfloat16* _xh = st_hi; \
        const __nv_bfloat16* _xl = st_lo; \
        if (KSEG == 2 && _kg >= 512) { _xh = dy_hi; _xl = dy_lo; } \
        int _kk = _kg & 511; \
        uint32_t _st = smb + (STG) * STAGE_HALVES * 2; \
        _Pragma("unroll") \
        for (int _i = 0; _i < 4; _i++) { \
            int _gi = _i * 256 + tid; \
            int _hf = _gi >> 9; int _e = _gi & 511; \
            int _row = _e >> 2, _g = _e & 3; \
            const __nv_bfloat16* _src = (_hf ? Wlo : Whi) \
                + (size_t)(mt * 128 + _row) * lda + _kg + _g * 8; \
            cp16(_st + ((_hf ? AL_OFF : 0) + _row * A_SH + _g * 8) * 2, _src); \
        } \
        _Pragma("unroll") \
        for (int _i = 0; _i < 4; _i++) { \
            int _gi = _i * 256 + tid; \
            int _hf = _gi >> 9; int _e = _gi & 511; \
            int _row = _e >> 4, _g = _e & 15; \
            const __nv_bfloat16* _src = (_hf ? _xl : _xh) \
                + ((size_t)b * HH + _kk + _row) * SS + n0 + _g * 8; \
            cp16(_st + ((_hf ? BL_OFF : BH_OFF) + _row * B_SH + _g * 8) * 2, _src); \
        } \
        CP_COMMIT(); \
    } while (0)

        ISSUE_CHUNK(0, 0);

#pragma unroll 1
        for (int ch = 0; ch < NCH; ch++) {
            if (ch + 1 < NCH) ISSUE_CHUNK(ch + 1, (ch + 1) & 1);
            if (ch + 1 < NCH) CP_WAIT(1); else CP_WAIT(0);
            __syncthreads();

            const uint32_t stb = smb + (ch & 1) * STAGE_HALVES * 2;
            const uint32_t a_addr = stb + a_lane;
            const uint32_t b_addr = stb + b_lane;

#pragma unroll
            for (int ks = 0; ks < 2; ks++) {
                const uint32_t ka = a_addr + ks * 32;            // +16 halves
                const uint32_t kb = b_addr + ks * 16 * B_SH * 2; // +16 k rows
                uint32_t ah[4][4], al[4][4], bh[4][2], bl[4][2];
#pragma unroll
                for (int mf = 0; mf < 4; mf++)
                    ldm_x4(ah[mf], ka + mf * 16 * A_SH * 2);
#pragma unroll
                for (int nf = 0; nf < 4; nf++)
                    ldm_x2t(bh[nf], kb + nf * 16);
#pragma unroll
                for (int mf = 0; mf < 4; mf++)
#pragma unroll
                    for (int nf = 0; nf < 4; nf++)
                        mma_bf16(acc[mf][nf], ah[mf], bh[nf]);
#pragma unroll
                for (int nf = 0; nf < 4; nf++)
                    ldm_x2t(bl[nf], kb + (BL_OFF - BH_OFF) * 2 + nf * 16);
#pragma unroll
                for (int mf = 0; mf < 4; mf++)
#pragma unroll
                    for (int nf = 0; nf < 4; nf++)
                        mma_bf16(acc[mf][nf], ah[mf], bl[nf]);
#pragma unroll
                for (int mf = 0; mf < 4; mf++)
                    ldm_x4(al[mf], ka + AL_OFF * 2 + mf * 16 * A_SH * 2);
#pragma unroll
                for (int mf = 0; mf < 4; mf++)
#pragma unroll
                    for (int nf = 0; nf < 4; nf++)
                        mma_bf16(acc[mf][nf], al[mf], bh[nf]);
            }
            __syncthreads();
        }

        // ---- epilogue for this m-tile ----
        float p0[4], p1[4];
#pragma unroll
        for (int nf = 0; nf < 4; nf++) { p0[nf] = 0.0f; p1[nf] = 0.0f; }
#pragma unroll
        for (int mf = 0; mf < 4; mf++) {
            int h0 = mt * 128 + wm * 64 + mf * 16 + gid;
            float vv0 = vvec[h0], vv1 = vvec[h0 + 8];
            float av0 = addvec[b * HH + h0], av1 = addvec[b * HH + h0 + 8];
#pragma unroll
            for (int nf = 0; nf < 4; nf++) {
                p0[nf] += vv0 * my_tanh(acc[mf][nf][0] + av0)
                        + vv1 * my_tanh(acc[mf][nf][2] + av1);
                p1[nf] += vv0 * my_tanh(acc[mf][nf][1] + av0)
                        + vv1 * my_tanh(acc[mf][nf][3] + av1);
            }
        }
#pragma unroll
        for (int nf = 0; nf < 4; nf++) {
            float a0 = p0[nf], a1 = p1[nf];
#pragma unroll
            for (int d = 4; d < 32; d <<= 1) {
                a0 += __shfl_xor_sync(0xffffffffu, a0, d);
                a1 += __shfl_xor_sync(0xffffffffu, a1, d);
            }
            if (gid == 0) {
                int c = wm * 128 + wn * 32 + nf * 8 + lt4 * 2;
                colacc[c] += a0;
                colacc[c + 1] += a1;
            }
        }
        __syncthreads();
    }

    if (tid < 128) outp[(size_t)b * SS + n0 + tid] = colacc[tid] + colacc[128 + tid];
#undef ISSUE_CHUNK
}

// ---------------- GRU ----------------
__global__ void gru_kernel(const float* __restrict__ last_output,
                           const float* __restrict__ last_hidden,
                           const float* __restrict__ emb_W,
                           const float* __restrict__ emb_b,
                           const float* __restrict__ Wih,
                           const float* __restrict__ Whh,
                           const float* __restrict__ bih,
                           const float* __restrict__ bhh,
                           float* __restrict__ hidden_out) {
    int b = blockIdx.x;
    int t = threadIdx.x;
    __shared__ float sx[HH], sh[HH];
    __shared__ float sgx[H3], sgh[H3];
    float o0 = last_output[b * 2 + 0];
    float o1 = last_output[b * 2 + 1];
    for (int j = t; j < HH; j += 256) {
        sx[j] = o0 * emb_W[j * 2 + 0] + o1 * emb_W[j * 2 + 1] + emb_b[j];
        sh[j] = last_hidden[b * HH + j];
    }
    __syncthreads();
    for (int j = t; j < H3; j += 256) {
        float ax = bih[j], ah = bhh[j];
        const float4* wi = (const float4*)(Wih + (size_t)j * HH);
        const float4* wh = (const float4*)(Whh + (size_t)j * HH);
#pragma unroll 4
        for (int k4 = 0; k4 < HH / 4; k4++) {
            float4 a = wi[k4];
            float4 c = wh[k4];
            int k = k4 * 4;
            ax += a.x * sx[k] + a.y * sx[k + 1] + a.z * sx[k + 2] + a.w * sx[k + 3];
            ah += c.x * sh[k] + c.y * sh[k + 1] + c.z * sh[k + 2] + c.w * sh[k + 3];
        }
        sgx[j] = ax;
        sgh[j] = ah;
    }
    __syncthreads();
    for (int j = t; j < HH; j += 256) {
        float r = my_sigmoid(sgx[j] + sgh[j]);
        float z = my_sigmoid(sgx[HH + j] + sgh[HH + j]);
        float n = my_tanh(sgx[2 * HH + j] + r * sgh[2 * HH + j]);
        float hn = (1.0f - z) * n + z * sh[j];
        g_hnew[b * HH + j] = hn;
        hidden_out[b * HH + j] = hn;
    }
}

// ---------------- matvec ----------------
__global__ void matvec_kernel(const float* __restrict__ M, int ldm, int off,
                              const float* __restrict__ vec,
                              float* __restrict__ out) {
    int b = blockIdx.y;
    int h0 = blockIdx.x * 64;
    int t = threadIdx.x;
    __shared__ float sv[HH];
    for (int k = t; k < HH; k += 256) sv[k] = vec[b * HH + k];
    __syncthreads();
    int hl = t >> 2, l4 = t & 3;
    int h = h0 + hl;
    const float* m = M + (size_t)h * ldm + off;
    float acc = 0.0f;
    for (int k = l4 * 4; k < HH; k += 16) {
        float4 mv = *(const float4*)(m + k);
        acc += mv.x * sv[k] + mv.y * sv[k + 1] + mv.z * sv[k + 2] + mv.w * sv[k + 3];
    }
    acc += __shfl_xor_sync(0xffffffffu, acc, 1);
    acc += __shfl_xor_sync(0xffffffffu, acc, 2);
    if (l4 == 0) out[b * HH + h] = acc;
}

// ---------------- softmax ----------------
__global__ void softmax_kernel(const float* __restrict__ scores,
                               float* __restrict__ attns) {
    int b = blockIdx.x;
    int t = threadIdx.x;
    __shared__ float sm[256];
    float v0 = scores[b * SS + t];
    float v1 = scores[b * SS + 256 + t];
    sm[t] = fmaxf(v0, v1);
    __syncthreads();
    for (int off = 128; off > 0; off >>= 1) {
        if (t < off) sm[t] = fmaxf(sm[t], sm[t + off]);
        __syncthreads();
    }
    float mx = sm[0];
    __syncthreads();
    float e0 = __expf(v0 - mx);
    float e1 = __expf(v1 - mx);
    sm[t] = e0 + e1;
    __syncthreads();
    for (int off = 128; off > 0; off >>= 1) {
        if (t < off) sm[t] += sm[t + off];
        __syncthreads();
    }
    float inv = 1.0f / sm[0];
    attns[b * SS + t] = e0 * inv;
    attns[b * SS + 256 + t] = e1 * inv;
}

// ---------------- context ----------------
__global__ void context_kernel(const float* __restrict__ st,
                               const float* __restrict__ attns,
                               float* __restrict__ ctx) {
    int b = blockIdx.y;
    int h0 = blockIdx.x * 8;
    int w = threadIdx.x >> 5, l = threadIdx.x & 31;
    __shared__ float sa[SS];
    for (int s = threadIdx.x; s < SS; s += 256) sa[s] = attns[b * SS + s];
    __syncthreads();
    int h = h0 + w;
    const float* row = st + (size_t)b * HH * SS + (size_t)h * SS;
    float acc = 0.0f;
    for (int s = l * 4; s < SS; s += 128) {
        float4 r4 = *(const float4*)(row + s);
        acc += r4.x * sa[s] + r4.y * sa[s + 1] + r4.z * sa[s + 2] + r4.w * sa[s + 3];
    }
#pragma unroll
    for (int off = 16; off > 0; off >>= 1)
        acc += __shfl_xor_sync(0xffffffffu, acc, off);
    if (l == 0) ctx[b * HH + h] = acc;
}

// ---------------- launch ----------------
extern "C" void kernel_launch(void* const* d_in, const int* in_sizes, int n_in,
                              void* d_out, int out_size) {
    const float* st     = (const float*)d_in[0];
    const float* dy     = (const float*)d_in[1];
    const float* lo     = (const float*)d_in[2];
    const float* lh     = (const float*)d_in[3];
    const float* embW   = (const float*)d_in[4];
    const float* embb   = (const float*)d_in[5];
    const float* Wih    = (const float*)d_in[6];
    const float* Whh    = (const float*)d_in[7];
    const float* bih    = (const float*)d_in[8];
    const float* bhh    = (const float*)d_in[9];
    const float* attn_v = (const float*)d_in[10];
    const float* attn_W = (const float*)d_in[11];
    const float* dec_v  = (const float*)d_in[12];
    const float* dec_W  = (const float*)d_in[13];
    float* out = (float*)d_out;

    float *p_hnew, *p_hc, *p_scores, *p_attns, *p_ctx, *p_cd2;
    cudaGetSymbolAddress((void**)&p_hnew, g_hnew);
    cudaGetSymbolAddress((void**)&p_hc, g_hc);
    cudaGetSymbolAddress((void**)&p_scores, g_scores);
    cudaGetSymbolAddress((void**)&p_attns, g_attns);
    cudaGetSymbolAddress((void**)&p_ctx, g_context);
    cudaGetSymbolAddress((void**)&p_cd2, g_cd2);

    __nv_bfloat16 *psth, *pstl, *pdyh, *pdyl, *pWabh, *pWabl, *pWdh, *pWdl;
    cudaGetSymbolAddress((void**)&psth, g_st_hi);
    cudaGetSymbolAddress((void**)&pstl, g_st_lo);
    cudaGetSymbolAddress((void**)&pdyh, g_dy_hi);
    cudaGetSymbolAddress((void**)&pdyl, g_dy_lo);
    cudaGetSymbolAddress((void**)&pWabh, g_Wab_hi);
    cudaGetSymbolAddress((void**)&pWabl, g_Wab_lo);
    cudaGetSymbolAddress((void**)&pWdh, g_Wd_hi);
    cudaGetSymbolAddress((void**)&pWdl, g_Wd_lo);

    cudaFuncSetAttribute(gemm_bf16_kernel<2>,
                         cudaFuncAttributeMaxDynamicSharedMemorySize, SMEM_BYTES);
    cudaFuncSetAttribute(gemm_bf16_kernel<1>,
                         cudaFuncAttributeMaxDynamicSharedMemorySize, SMEM_BYTES);

    // operand preparation (bf16 hi/lo split)
    prep_w<<<768, 256>>>(attn_W, dec_W);
    prep_enc<<<4096, 256>>>(st, dy);

    // 1. embedding + GRU -> h_new (also writes hidden output)
    gru_kernel<<<BB, 256>>>(lo, lh, embW, embb, Wih, Whh, bih, bhh, out + BB * SS);

    // 2. hc[b,h] = h_new @ Wc^T  (Wc = attn_W[:, 2H:3H])
    matvec_kernel<<<dim3(8, BB), 256>>>(attn_W, H3, 2 * HH, p_hnew, p_hc);

    // 3. scores[b,s] = attn_v . tanh(Wa@st + Wb@dy + hc)   (K=1024 fused)
    gemm_bf16_kernel<2><<<dim3(4, BB), 256, SMEM_BYTES>>>(
        pWabh, pWabl, 1024, psth, pstl, pdyh, pdyl, p_hc, attn_v, p_scores);

    // 4. softmax
    softmax_kernel<<<BB, 256>>>(p_scores, p_attns);

    // 5. context
    context_kernel<<<dim3(HH / 8, BB), 256>>>(st, p_attns, p_ctx);

    // 6. cd2[b,h] = context @ Wd2^T (Wd2 = dec_W[:, H:2H])
    matvec_kernel<<<dim3(8, BB), 256>>>(dec_W, 2 * HH, HH, p_ctx, p_cd2);

    // 7. outputs[b,s] = dec_v . tanh(Wd1@st + cd2)
    gemm_bf16_kernel<1><<<dim3(4, BB), 256, SMEM_BYTES>>>(
        pWdh, pWdl, 512, psth, pstl, psth, pstl, p_cd2, dec_v, out);
}

// round 7
// speedup vs baseline: 2.8393x; 1.3010x over previous
#include <cuda_runtime.h>
#include <cuda_fp16.h>
#include <cstdint>

#define BB 256
#define HH 512
#define SS 512
#define H3 1536

// ---------------- scratch ----------------
__device__ float g_hnew[BB * HH];
__device__ float g_hc[BB * HH];
__device__ float g_scores[BB * SS];
__device__ float g_attns[BB * SS];
__device__ float g_context[BB * HH];
__device__ float g_cd2[BB * HH];

// pre-converted fp16 operands (X: hi only; W: hi + lo split)
__device__ __half g_st_hi[BB * HH * SS];
__device__ __half g_dy_hi[BB * HH * SS];
__device__ __half g_Wab_hi[HH * 1024], g_Wab_lo[HH * 1024];
__device__ __half g_Wd_hi[HH * HH],    g_Wd_lo[HH * HH];

// ---------------- math ----------------
__device__ __forceinline__ float my_tanh(float x) {
    float ax = fabsf(x);
    float e = __expf(-2.0f * ax);
    float r = __fdividef(1.0f - e, 1.0f + e);
    return copysignf(r, x);
}
__device__ __forceinline__ float my_sigmoid(float x) {
    return 1.0f / (1.0f + __expf(-x));
}

// ---------------- PTX helpers ----------------
__device__ __forceinline__ uint32_t smem_u32(const void* p) {
    uint32_t a;
    asm("{ .reg .u64 t; cvta.to.shared.u64 t, %1; cvt.u32.u64 %0, t; }" : "=r"(a) : "l"(p));
    return a;
}
__device__ __forceinline__ void cp16(uint32_t dst, const void* src) {
    asm volatile("cp.async.cg.shared.global [%0], [%1], 16;" :: "r"(dst), "l"(src));
}
#define CP_COMMIT() asm volatile("cp.async.commit_group;" ::: "memory")
#define CP_WAIT(n)  asm volatile("cp.async.wait_group %0;" :: "n"(n) : "memory")

__device__ __forceinline__ void ldm_x4(uint32_t* r, uint32_t a) {
    asm volatile("ldmatrix.sync.aligned.m8n8.x4.shared.b16 {%0,%1,%2,%3}, [%4];"
        : "=r"(r[0]), "=r"(r[1]), "=r"(r[2]), "=r"(r[3]) : "r"(a));
}
__device__ __forceinline__ void ldm_x2t(uint32_t* r, uint32_t a) {
    asm volatile("ldmatrix.sync.aligned.m8n8.x2.trans.shared.b16 {%0,%1}, [%2];"
        : "=r"(r[0]), "=r"(r[1]) : "r"(a));
}
__device__ __forceinline__ void mma_fp16(float* d, const uint32_t* a, const uint32_t* b) {
    asm volatile(
        "mma.sync.aligned.m16n8k16.row.col.f32.f16.f16.f32 "
        "{%0,%1,%2,%3}, {%4,%5,%6,%7}, {%8,%9}, {%0,%1,%2,%3};"
        : "+f"(d[0]), "+f"(d[1]), "+f"(d[2]), "+f"(d[3])
        : "r"(a[0]), "r"(a[1]), "r"(a[2]), "r"(a[3]), "r"(b[0]), "r"(b[1]));
}

// ---------------- tile config (units: fp16 halves) ----------------
#define TK 32
#define A_SH 40            /* A smem row stride: 32 + 8 pad  */
#define B_SH 136           /* B smem row stride: 128 + 8 pad */
#define A_HALVES (128 * A_SH)           /* 5120 */
#define B_HALVES (TK * B_SH)            /* 4352 */
#define AL_OFF A_HALVES                  /* 5120  */
#define BH_OFF (2 * A_HALVES)            /* 10240 */
#define STAGE_HALVES (2 * A_HALVES + B_HALVES) /* 14592 */
#define SMEM_BYTES (2 * STAGE_HALVES * 2 + 256 * 4) /* 59392 */

// ---------------- prep kernels ----------------
__global__ void prep_w(const float* __restrict__ attn_W,
                       const float* __restrict__ dec_W) {
    int t = blockIdx.x * blockDim.x + threadIdx.x;  // 768*256 = 196608
#pragma unroll
    for (int i = 0; i < 4; i++) {
        int id = t + i * 196608;  // 0..786431
        float x;
        __half *dh, *dl;
        int e;
        if (id < 524288) {  // [Wa|Wb]: 512 x 1024
            int h = id >> 10, k = id & 1023;
            x = attn_W[h * H3 + k];
            dh = g_Wab_hi; dl = g_Wab_lo; e = id;
        } else {            // Wd1: 512 x 512
            e = id - 524288;
            int h = e >> 9, k = e & 511;
            x = dec_W[h * 1024 + k];
            dh = g_Wd_hi; dl = g_Wd_lo;
        }
        __half hi = __float2half_rn(x);
        dh[e] = hi;
        dl[e] = __float2half_rn(x - __half2float(hi));
    }
}

__global__ void prep_enc(const float* __restrict__ st,
                         const float* __restrict__ dy) {
    size_t nth = (size_t)gridDim.x * blockDim.x;
    const size_t NG = 2ull * 16777216ull;  // float4 groups across both tensors
    for (size_t g = (size_t)blockIdx.x * blockDim.x + threadIdx.x; g < NG; g += nth) {
        bool isdy = g >= 16777216ull;
        const float* src = isdy ? dy : st;
        __half* dh = isdy ? g_dy_hi : g_st_hi;
        size_t off = (g & 16777215ull) * 4;
        float4 v = *(const float4*)(src + off);
        __half2 h01 = __floats2half2_rn(v.x, v.y);
        __half2 h23 = __floats2half2_rn(v.z, v.w);
        uint2 uh;
        uh.x = *reinterpret_cast<unsigned*>(&h01);
        uh.y = *reinterpret_cast<unsigned*>(&h23);
        *(uint2*)(dh + off) = uh;
    }
}

// ============================================================================
// fp16 HMMA GEMM + fused v.tanh(.) reduce.
//   outp[b, n0+c] = sum_h vvec[h] * tanh( sum_k W[h,k]*X(k)[k%512, n0+c] + addvec[b,h] )
// KSEG=2: K=1024, X = st (k<512) then dy. KSEG=1: K=512, X = st.
// Grid (4 n-tiles, BB); CTA loops 4 m-tiles; 8 warps, warp tile 64m x 32n.
// 2-term split precision: W = Whi + Wlo (fp16 pair), X ~= Xhi (fp16);
// D ~= Whi.Xhi + Wlo.Xhi  (dropped W.Xlo term ~2^-11 rel, averages to ~1e-4).
// ============================================================================
template <int KSEG>
__global__ __launch_bounds__(256, 2) void gemm_fp16_kernel(
    const __half* __restrict__ Whi, const __half* __restrict__ Wlo,
    int lda,
    const __half* __restrict__ st_hi, const __half* __restrict__ dy_hi,
    const float* __restrict__ addvec, const float* __restrict__ vvec,
    float* __restrict__ outp) {
    extern __shared__ char smch[];
    const uint32_t smb = smem_u32(smch);
    float* colacc = (float*)(smch + 2 * STAGE_HALVES * 2);

    const int tid = threadIdx.x;
    const int lane = tid & 31;
    const int wid = tid >> 5;
    const int wm = wid >> 2;   // 0..1
    const int wn = wid & 3;    // 0..3
    const int gid = lane >> 2; // 0..7
    const int lt4 = lane & 3;  // 0..3
    const int n0 = blockIdx.x * 128;
    const int b = blockIdx.y;

    if (tid < 256) colacc[tid] = 0.0f;
    __syncthreads();

    const int NCH = KSEG * 16;

    // fragment base addresses (lane-dependent, stage-relative, bytes)
    const uint32_t a_lane = ((wm * 64 + (lane & 15)) * A_SH + (lane >> 4) * 8) * 2;
    const uint32_t b_lane = (BH_OFF + (lane & 15) * B_SH + wn * 32) * 2;

#pragma unroll 1
    for (int mt = 0; mt < 4; mt++) {
        float acc[4][4][4];
#pragma unroll
        for (int i = 0; i < 4; i++)
#pragma unroll
            for (int j = 0; j < 4; j++)
#pragma unroll
                for (int q = 0; q < 4; q++) acc[i][j][q] = 0.0f;

#define ISSUE_CHUNK(CH, STG) do { \
        int _kg = (CH) * TK; \
        const __half* _xh = (KSEG == 2 && _kg >= 512) ? dy_hi : st_hi; \
        int _kk = _kg & 511; \
        uint32_t _st = smb + (STG) * STAGE_HALVES * 2; \
        _Pragma("unroll") \
        for (int _i = 0; _i < 4; _i++) { \
            int _gi = _i * 256 + tid; \
            int _hf = _gi >> 9; int _e = _gi & 511; \
            int _row = _e >> 2, _g = _e & 3; \
            const __half* _src = (_hf ? Wlo : Whi) \
                + (size_t)(mt * 128 + _row) * lda + _kg + _g * 8; \
            cp16(_st + ((_hf ? AL_OFF : 0) + _row * A_SH + _g * 8) * 2, _src); \
        } \
        _Pragma("unroll") \
        for (int _i = 0; _i < 2; _i++) { \
            int _gi = _i * 256 + tid; \
            int _row = _gi >> 4, _g = _gi & 15; \
            const __half* _src = _xh \
                + ((size_t)b * HH + _kk + _row) * SS + n0 + _g * 8; \
            cp16(_st + (BH_OFF + _row * B_SH + _g * 8) * 2, _src); \
        } \
        CP_COMMIT(); \
    } while (0)

        ISSUE_CHUNK(0, 0);

#pragma unroll 1
        for (int ch = 0; ch < NCH; ch++) {
            if (ch + 1 < NCH) ISSUE_CHUNK(ch + 1, (ch + 1) & 1);
            if (ch + 1 < NCH) CP_WAIT(1); else CP_WAIT(0);
            __syncthreads();

            const uint32_t stb = smb + (ch & 1) * STAGE_HALVES * 2;
            const uint32_t a_addr = stb + a_lane;
            const uint32_t b_addr = stb + b_lane;

#pragma unroll
            for (int ks = 0; ks < 2; ks++) {
                const uint32_t ka = a_addr + ks * 32;            // +16 halves
                const uint32_t kb = b_addr + ks * 16 * B_SH * 2; // +16 k rows
                uint32_t ah[4][4], al[4][4], bh[4][2];
#pragma unroll
                for (int mf = 0; mf < 4; mf++)
                    ldm_x4(ah[mf], ka + mf * 16 * A_SH * 2);
#pragma unroll
                for (int nf = 0; nf < 4; nf++)
                    ldm_x2t(bh[nf], kb + nf * 16);
#pragma unroll
                for (int mf = 0; mf < 4; mf++)
#pragma unroll
                    for (int nf = 0; nf < 4; nf++)
                        mma_fp16(acc[mf][nf], ah[mf], bh[nf]);
#pragma unroll
                for (int mf = 0; mf < 4; mf++)
                    ldm_x4(al[mf], ka + AL_OFF * 2 + mf * 16 * A_SH * 2);
#pragma unroll
                for (int mf = 0; mf < 4; mf++)
#pragma unroll
                    for (int nf = 0; nf < 4; nf++)
                        mma_fp16(acc[mf][nf], al[mf], bh[nf]);
            }
            __syncthreads();
        }

        // ---- epilogue for this m-tile ----
        float p0[4], p1[4];
#pragma unroll
        for (int nf = 0; nf < 4; nf++) { p0[nf] = 0.0f; p1[nf] = 0.0f; }
#pragma unroll
        for (int mf = 0; mf < 4; mf++) {
            int h0 = mt * 128 + wm * 64 + mf * 16 + gid;
            float vv0 = vvec[h0], vv1 = vvec[h0 + 8];
            float av0 = addvec[b * HH + h0], av1 = addvec[b * HH + h0 + 8];
#pragma unroll
            for (int nf = 0; nf < 4; nf++) {
                p0[nf] += vv0 * my_tanh(acc[mf][nf][0] + av0)
                        + vv1 * my_tanh(acc[mf][nf][2] + av1);
                p1[nf] += vv0 * my_tanh(acc[mf][nf][1] + av0)
                        + vv1 * my_tanh(acc[mf][nf][3] + av1);
            }
        }
#pragma unroll
        for (int nf = 0; nf < 4; nf++) {
            float a0 = p0[nf], a1 = p1[nf];
#pragma unroll
            for (int d = 4; d < 32; d <<= 1) {
                a0 += __shfl_xor_sync(0xffffffffu, a0, d);
                a1 += __shfl_xor_sync(0xffffffffu, a1, d);
            }
            if (gid == 0) {
                int c = wm * 128 + wn * 32 + nf * 8 + lt4 * 2;
                colacc[c] += a0;
                colacc[c + 1] += a1;
            }
        }
        __syncthreads();
    }

    if (tid < 128) outp[(size_t)b * SS + n0 + tid] = colacc[tid] + colacc[128 + tid];
#undef ISSUE_CHUNK
}

// ---------------- GRU ----------------
__global__ void gru_kernel(const float* __restrict__ last_output,
                           const float* __restrict__ last_hidden,
                           const float* __restrict__ emb_W,
                           const float* __restrict__ emb_b,
                           const float* __restrict__ Wih,
                           const float* __restrict__ Whh,
                           const float* __restrict__ bih,
                           const float* __restrict__ bhh,
                           float* __restrict__ hidden_out) {
    int b = blockIdx.x;
    int t = threadIdx.x;
    __shared__ float sx[HH], sh[HH];
    __shared__ float sgx[H3], sgh[H3];
    float o0 = last_output[b * 2 + 0];
    float o1 = last_output[b * 2 + 1];
    for (int j = t; j < HH; j += 256) {
        sx[j] = o0 * emb_W[j * 2 + 0] + o1 * emb_W[j * 2 + 1] + emb_b[j];
        sh[j] = last_hidden[b * HH + j];
    }
    __syncthreads();
    for (int j = t; j < H3; j += 256) {
        float ax = bih[j], ah = bhh[j];
        const float4* wi = (const float4*)(Wih + (size_t)j * HH);
        const float4* wh = (const float4*)(Whh + (size_t)j * HH);
#pragma unroll 4
        for (int k4 = 0; k4 < HH / 4; k4++) {
            float4 a = wi[k4];
            float4 c = wh[k4];
            int k = k4 * 4;
            ax += a.x * sx[k] + a.y * sx[k + 1] + a.z * sx[k + 2] + a.w * sx[k + 3];
            ah += c.x * sh[k] + c.y * sh[k + 1] + c.z * sh[k + 2] + c.w * sh[k + 3];
        }
        sgx[j] = ax;
        sgh[j] = ah;
    }
    __syncthreads();
    for (int j = t; j < HH; j += 256) {
        float r = my_sigmoid(sgx[j] + sgh[j]);
        float z = my_sigmoid(sgx[HH + j] + sgh[HH + j]);
        float n = my_tanh(sgx[2 * HH + j] + r * sgh[2 * HH + j]);
        float hn = (1.0f - z) * n + z * sh[j];
        g_hnew[b * HH + j] = hn;
        hidden_out[b * HH + j] = hn;
    }
}

// ---------------- matvec ----------------
__global__ void matvec_kernel(const float* __restrict__ M, int ldm, int off,
                              const float* __restrict__ vec,
                              float* __restrict__ out) {
    int b = blockIdx.y;
    int h0 = blockIdx.x * 64;
    int t = threadIdx.x;
    __shared__ float sv[HH];
    for (int k = t; k < HH; k += 256) sv[k] = vec[b * HH + k];
    __syncthreads();
    int hl = t >> 2, l4 = t & 3;
    int h = h0 + hl;
    const float* m = M + (size_t)h * ldm + off;
    float acc = 0.0f;
    for (int k = l4 * 4; k < HH; k += 16) {
        float4 mv = *(const float4*)(m + k);
        acc += mv.x * sv[k] + mv.y * sv[k + 1] + mv.z * sv[k + 2] + mv.w * sv[k + 3];
    }
    acc += __shfl_xor_sync(0xffffffffu, acc, 1);
    acc += __shfl_xor_sync(0xffffffffu, acc, 2);
    if (l4 == 0) out[b * HH + h] = acc;
}

// ---------------- softmax ----------------
__global__ void softmax_kernel(const float* __restrict__ scores,
                               float* __restrict__ attns) {
    int b = blockIdx.x;
    int t = threadIdx.x;
    __shared__ float sm[256];
    float v0 = scores[b * SS + t];
    float v1 = scores[b * SS + 256 + t];
    sm[t] = fmaxf(v0, v1);
    __syncthreads();
    for (int off = 128; off > 0; off >>= 1) {
        if (t < off) sm[t] = fmaxf(sm[t], sm[t + off]);
        __syncthreads();
    }
    float mx = sm[0];
    __syncthreads();
    float e0 = __expf(v0 - mx);
    float e1 = __expf(v1 - mx);
    sm[t] = e0 + e1;
    __syncthreads();
    for (int off = 128; off > 0; off >>= 1) {
        if (t < off) sm[t] += sm[t + off];
        __syncthreads();
    }
    float inv = 1.0f / sm[0];
    attns[b * SS + t] = e0 * inv;
    attns[b * SS + 256 + t] = e1 * inv;
}

// ---------------- context ----------------
__global__ void context_kernel(const float* __restrict__ st,
                               const float* __restrict__ attns,
                               float* __restrict__ ctx) {
    int b = blockIdx.y;
    int h0 = blockIdx.x * 8;
    int w = threadIdx.x >> 5, l = threadIdx.x & 31;
    __shared__ float sa[SS];
    for (int s = threadIdx.x; s < SS; s += 256) sa[s] = attns[b * SS + s];
    __syncthreads();
    int h = h0 + w;
    const float* row = st + (size_t)b * HH * SS + (size_t)h * SS;
    float acc = 0.0f;
    for (int s = l * 4; s < SS; s += 128) {
        float4 r4 = *(const float4*)(row + s);
        acc += r4.x * sa[s] + r4.y * sa[s + 1] + r4.z * sa[s + 2] + r4.w * sa[s + 3];
    }
#pragma unroll
    for (int off = 16; off > 0; off >>= 1)
        acc += __shfl_xor_sync(0xffffffffu, acc, off);
    if (l == 0) ctx[b * HH + h] = acc;
}

// ---------------- launch ----------------
extern "C" void kernel_launch(void* const* d_in, const int* in_sizes, int n_in,
                              void* d_out, int out_size) {
    const float* st     = (const float*)d_in[0];
    const float* dy     = (const float*)d_in[1];
    const float* lo     = (const float*)d_in[2];
    const float* lh     = (const float*)d_in[3];
    const float* embW   = (const float*)d_in[4];
    const float* embb   = (const float*)d_in[5];
    const float* Wih    = (const float*)d_in[6];
    const float* Whh    = (const float*)d_in[7];
    const float* bih    = (const float*)d_in[8];
    const float* bhh    = (const float*)d_in[9];
    const float* attn_v = (const float*)d_in[10];
    const float* attn_W = (const float*)d_in[11];
    const float* dec_v  = (const float*)d_in[12];
    const float* dec_W  = (const float*)d_in[13];
    float* out = (float*)d_out;

    float *p_hnew, *p_hc, *p_scores, *p_attns, *p_ctx, *p_cd2;
    cudaGetSymbolAddress((void**)&p_hnew, g_hnew);
    cudaGetSymbolAddress((void**)&p_hc, g_hc);
    cudaGetSymbolAddress((void**)&p_scores, g_scores);
    cudaGetSymbolAddress((void**)&p_attns, g_attns);
    cudaGetSymbolAddress((void**)&p_ctx, g_context);
    cudaGetSymbolAddress((void**)&p_cd2, g_cd2);

    __half *psth, *pdyh, *pWabh, *pWabl, *pWdh, *pWdl;
    cudaGetSymbolAddress((void**)&psth, g_st_hi);
    cudaGetSymbolAddress((void**)&pdyh, g_dy_hi);
    cudaGetSymbolAddress((void**)&pWabh, g_Wab_hi);
    cudaGetSymbolAddress((void**)&pWabl, g_Wab_lo);
    cudaGetSymbolAddress((void**)&pWdh, g_Wd_hi);
    cudaGetSymbolAddress((void**)&pWdl, g_Wd_lo);

    cudaFuncSetAttribute(gemm_fp16_kernel<2>,
                         cudaFuncAttributeMaxDynamicSharedMemorySize, SMEM_BYTES);
    cudaFuncSetAttribute(gemm_fp16_kernel<1>,
                         cudaFuncAttributeMaxDynamicSharedMemorySize, SMEM_BYTES);

    // operand preparation (fp16; W hi/lo split, X hi only)
    prep_w<<<768, 256>>>(attn_W, dec_W);
    prep_enc<<<4096, 256>>>(st, dy);

    // 1. embedding + GRU -> h_new (also writes hidden output)
    gru_kernel<<<BB, 256>>>(lo, lh, embW, embb, Wih, Whh, bih, bhh, out + BB * SS);

    // 2. hc[b,h] = h_new @ Wc^T  (Wc = attn_W[:, 2H:3H])
    matvec_kernel<<<dim3(8, BB), 256>>>(attn_W, H3, 2 * HH, p_hnew, p_hc);

    // 3. scores[b,s] = attn_v . tanh(Wa@st + Wb@dy + hc)   (K=1024 fused)
    gemm_fp16_kernel<2><<<dim3(4, BB), 256, SMEM_BYTES>>>(
        pWabh, pWabl, 1024, psth, pdyh, p_hc, attn_v, p_scores);

    // 4. softmax
    softmax_kernel<<<BB, 256>>>(p_scores, p_attns);

    // 5. context
    context_kernel<<<dim3(HH / 8, BB), 256>>>(st, p_attns, p_ctx);

    // 6. cd2[b,h] = context @ Wd2^T (Wd2 = dec_W[:, H:2H])
    matvec_kernel<<<dim3(8, BB), 256>>>(dec_W, 2 * HH, HH, p_ctx, p_cd2);

    // 7. outputs[b,s] = dec_v . tanh(Wd1@st + cd2)
    gemm_fp16_kernel<1><<<dim3(4, BB), 256, SMEM_BYTES>>>(
        pWdh, pWdl, 512, psth, psth, p_cd2, dec_v, out);
}

// round 8
// speedup vs baseline: 4.7862x; 1.6857x over previous
#include <cuda_runtime.h>
#include <cuda_fp16.h>
#include <cstdint>

#define BB 256
#define HH 512
#define SS 512
#define H3 1536

// ---------------- scratch ----------------
__device__ float g_hnew[BB * HH];
__device__ float g_hc[BB * HH];
__device__ float g_scores[BB * SS];
__device__ float g_attns[BB * SS];
__device__ float g_context[BB * HH];
__device__ float g_cd2[BB * HH];

// pre-converted fp16 operands
__device__ __half g_st_hi[BB * HH * SS];
__device__ __half g_dy_hi[BB * HH * SS];
__device__ __half g_Wab_hi[HH * 1024];
__device__ __half g_Wd_hi[HH * HH];

// ---------------- math ----------------
__device__ __forceinline__ float my_tanh(float x) {
    float ax = fabsf(x);
    float e = __expf(-2.0f * ax);
    float r = __fdividef(1.0f - e, 1.0f + e);
    return copysignf(r, x);
}
__device__ __forceinline__ float my_sigmoid(float x) {
    return 1.0f / (1.0f + __expf(-x));
}

// ---------------- PTX helpers ----------------
__device__ __forceinline__ uint32_t smem_u32(const void* p) {
    uint32_t a;
    asm("{ .reg .u64 t; cvta.to.shared.u64 t, %1; cvt.u32.u64 %0, t; }" : "=r"(a) : "l"(p));
    return a;
}
__device__ __forceinline__ void cp16(uint32_t dst, const void* src) {
    asm volatile("cp.async.cg.shared.global [%0], [%1], 16;" :: "r"(dst), "l"(src));
}
#define CP_COMMIT() asm volatile("cp.async.commit_group;" ::: "memory")
#define CP_WAIT(n)  asm volatile("cp.async.wait_group %0;" :: "n"(n) : "memory")

__device__ __forceinline__ void ldm_x4(uint32_t* r, uint32_t a) {
    asm volatile("ldmatrix.sync.aligned.m8n8.x4.shared.b16 {%0,%1,%2,%3}, [%4];"
        : "=r"(r[0]), "=r"(r[1]), "=r"(r[2]), "=r"(r[3]) : "r"(a));
}
__device__ __forceinline__ void ldm_x2t(uint32_t* r, uint32_t a) {
    asm volatile("ldmatrix.sync.aligned.m8n8.x2.trans.shared.b16 {%0,%1}, [%2];"
        : "=r"(r[0]), "=r"(r[1]) : "r"(a));
}
__device__ __forceinline__ void mma_fp16(float* d, const uint32_t* a, const uint32_t* b) {
    asm volatile(
        "mma.sync.aligned.m16n8k16.row.col.f32.f16.f16.f32 "
        "{%0,%1,%2,%3}, {%4,%5,%6,%7}, {%8,%9}, {%0,%1,%2,%3};"
        : "+f"(d[0]), "+f"(d[1]), "+f"(d[2]), "+f"(d[3])
        : "r"(a[0]), "r"(a[1]), "r"(a[2]), "r"(a[3]), "r"(b[0]), "r"(b[1]));
}

// ---------------- tile config (units: fp16 halves) ----------------
#define TK 32
#define A_SH 40
#define B_SH 136
#define A_HALVES (128 * A_SH)           /* 5120 */
#define B_HALVES (TK * B_SH)            /* 4352 */
#define BH_OFF A_HALVES
#define STAGE_HALVES (A_HALVES + B_HALVES) /* 9472 */
#define SMEM_BYTES (2 * STAGE_HALVES * 2 + 256 * 4) /* 38912 */

// ---------------- prep kernels ----------------
__global__ void prep_w(const float* __restrict__ attn_W,
                       const float* __restrict__ dec_W) {
    int t = blockIdx.x * blockDim.x + threadIdx.x;  // 768*256 = 196608
#pragma unroll
    for (int i = 0; i < 4; i++) {
        int id = t + i * 196608;  // 0..786431
        if (id < 524288) {  // [Wa|Wb]: 512 x 1024
            int h = id >> 10, k = id & 1023;
            g_Wab_hi[id] = __float2half_rn(attn_W[h * H3 + k]);
        } else {            // Wd1: 512 x 512
            int e = id - 524288;
            int h = e >> 9, k = e & 511;
            g_Wd_hi[e] = __float2half_rn(dec_W[h * 1024 + k]);
        }
    }
}

__global__ void prep_enc(const float* __restrict__ st,
                         const float* __restrict__ dy) {
    size_t nth = (size_t)gridDim.x * blockDim.x;
    const size_t NG = 2ull * 16777216ull;
    for (size_t g = (size_t)blockIdx.x * blockDim.x + threadIdx.x; g < NG; g += nth) {
        bool isdy = g >= 16777216ull;
        const float* src = isdy ? dy : st;
        __half* dh = isdy ? g_dy_hi : g_st_hi;
        size_t off = (g & 16777215ull) * 4;
        float4 v = *(const float4*)(src + off);
        __half2 h01 = __floats2half2_rn(v.x, v.y);
        __half2 h23 = __floats2half2_rn(v.z, v.w);
        uint2 uh;
        uh.x = *reinterpret_cast<unsigned*>(&h01);
        uh.y = *reinterpret_cast<unsigned*>(&h23);
        *(uint2*)(dh + off) = uh;
    }
}

// ============================================================================
// fp16 HMMA GEMM + fused v.tanh(.) reduce (single-term fp16).
// ============================================================================
template <int KSEG>
__global__ __launch_bounds__(256, 2) void gemm_fp16_kernel(
    const __half* __restrict__ W, int lda,
    const __half* __restrict__ st_hi, const __half* __restrict__ dy_hi,
    const float* __restrict__ addvec, const float* __restrict__ vvec,
    float* __restrict__ outp) {
    extern __shared__ char smch[];
    const uint32_t smb = smem_u32(smch);
    float* colacc = (float*)(smch + 2 * STAGE_HALVES * 2);

    const int tid = threadIdx.x;
    const int lane = tid & 31;
    const int wid = tid >> 5;
    const int wm = wid >> 2;   // 0..1
    const int wn = wid & 3;    // 0..3
    const int gid = lane >> 2; // 0..7
    const int lt4 = lane & 3;  // 0..3
    const int n0 = blockIdx.x * 128;
    const int b = blockIdx.y;

    if (tid < 256) colacc[tid] = 0.0f;
    __syncthreads();

    const int NCH = KSEG * 16;

    const uint32_t a_lane = ((wm * 64 + (lane & 15)) * A_SH + (lane >> 4) * 8) * 2;
    const uint32_t b_lane = (BH_OFF + (lane & 15) * B_SH + wn * 32) * 2;

#pragma unroll 1
    for (int mt = 0; mt < 4; mt++) {
        float acc[4][4][4];
#pragma unroll
        for (int i = 0; i < 4; i++)
#pragma unroll
            for (int j = 0; j < 4; j++)
#pragma unroll
                for (int q = 0; q < 4; q++) acc[i][j][q] = 0.0f;

#define ISSUE_CHUNK(CH, STG) do { \
        int _kg = (CH) * TK; \
        const __half* _xh = (KSEG == 2 && _kg >= 512) ? dy_hi : st_hi; \
        int _kk = _kg & 511; \
        uint32_t _st = smb + (STG) * STAGE_HALVES * 2; \
        _Pragma("unroll") \
        for (int _i = 0; _i < 2; _i++) { \
            int _gi = _i * 256 + tid; \
            int _row = _gi >> 2, _g = _gi & 3; \
            cp16(_st + (_row * A_SH + _g * 8) * 2, \
                 W + (size_t)(mt * 128 + _row) * lda + _kg + _g * 8); \
        } \
        _Pragma("unroll") \
        for (int _i = 0; _i < 2; _i++) { \
            int _gi = _i * 256 + tid; \
            int _row = _gi >> 4, _g = _gi & 15; \
            cp16(_st + (BH_OFF + _row * B_SH + _g * 8) * 2, \
                 _xh + ((size_t)b * HH + _kk + _row) * SS + n0 + _g * 8); \
        } \
        CP_COMMIT(); \
    } while (0)

        ISSUE_CHUNK(0, 0);

#pragma unroll 1
        for (int ch = 0; ch < NCH; ch++) {
            if (ch + 1 < NCH) ISSUE_CHUNK(ch + 1, (ch + 1) & 1);
            if (ch + 1 < NCH) CP_WAIT(1); else CP_WAIT(0);
            __syncthreads();

            const uint32_t stb = smb + (ch & 1) * STAGE_HALVES * 2;
            const uint32_t a_addr = stb + a_lane;
            const uint32_t b_addr = stb + b_lane;

#pragma unroll
            for (int ks = 0; ks < 2; ks++) {
                const uint32_t ka = a_addr + ks * 32;
                const uint32_t kb = b_addr + ks * 16 * B_SH * 2;
                uint32_t ah[4][4], bh[4][2];
#pragma unroll
                for (int mf = 0; mf < 4; mf++)
                    ldm_x4(ah[mf], ka + mf * 16 * A_SH * 2);
#pragma unroll
                for (int nf = 0; nf < 4; nf++)
                    ldm_x2t(bh[nf], kb + nf * 16);
#pragma unroll
                for (int mf = 0; mf < 4; mf++)
#pragma unroll
                    for (int nf = 0; nf < 4; nf++)
                        mma_fp16(acc[mf][nf], ah[mf], bh[nf]);
            }
            __syncthreads();
        }

        // ---- epilogue for this m-tile ----
        float p0[4], p1[4];
#pragma unroll
        for (int nf = 0; nf < 4; nf++) { p0[nf] = 0.0f; p1[nf] = 0.0f; }
#pragma unroll
        for (int mf = 0; mf < 4; mf++) {
            int h0 = mt * 128 + wm * 64 + mf * 16 + gid;
            float vv0 = vvec[h0], vv1 = vvec[h0 + 8];
            float av0 = addvec[b * HH + h0], av1 = addvec[b * HH + h0 + 8];
#pragma unroll
            for (int nf = 0; nf < 4; nf++) {
                p0[nf] += vv0 * my_tanh(acc[mf][nf][0] + av0)
                        + vv1 * my_tanh(acc[mf][nf][2] + av1);
                p1[nf] += vv0 * my_tanh(acc[mf][nf][1] + av0)
                        + vv1 * my_tanh(acc[mf][nf][3] + av1);
            }
        }
#pragma unroll
        for (int nf = 0; nf < 4; nf++) {
            float a0 = p0[nf], a1 = p1[nf];
#pragma unroll
            for (int d = 4; d < 32; d <<= 1) {
                a0 += __shfl_xor_sync(0xffffffffu, a0, d);
                a1 += __shfl_xor_sync(0xffffffffu, a1, d);
            }
            if (gid == 0) {
                int c = wm * 128 + wn * 32 + nf * 8 + lt4 * 2;
                colacc[c] += a0;
                colacc[c + 1] += a1;
            }
        }
        __syncthreads();
    }

    if (tid < 128) outp[(size_t)b * SS + n0 + tid] = colacc[tid] + colacc[128 + tid];
#undef ISSUE_CHUNK
}

// ---------------- GRU: grid (2 h-tiles, 32 batch-tiles), 8 batches/CTA ----
__global__ __launch_bounds__(256) void gru_kernel(
    const float* __restrict__ last_output,
    const float* __restrict__ last_hidden,
    const float* __restrict__ emb_W,
    const float* __restrict__ emb_b,
    const float* __restrict__ Wih,
    const float* __restrict__ Whh,
    const float* __restrict__ bih,
    const float* __restrict__ bhh,
    float* __restrict__ hidden_out) {
    int ht = blockIdx.x;          // 0..1
    int b0 = blockIdx.y * 8;
    int t = threadIdx.x;
    __shared__ float sx[8][512], sh[8][512];

    for (int i = t; i < 4096; i += 256) {
        int bb = i >> 9, k = i & 511;
        int b = b0 + bb;
        sx[bb][k] = last_output[b * 2] * emb_W[k * 2]
                  + last_output[b * 2 + 1] * emb_W[k * 2 + 1] + emb_b[k];
        sh[bb][k] = last_hidden[b * HH + k];
    }
    __syncthreads();

    int h = ht * 256 + t;
    float r8[8], z8[8];

#pragma unroll 1
    for (int gate = 0; gate < 3; gate++) {
        int j = gate * HH + h;
        float ax[8], ahh[8];
        float bx = bih[j], bh2 = bhh[j];
#pragma unroll
        for (int bb = 0; bb < 8; bb++) { ax[bb] = bx; ahh[bb] = bh2; }
        const float4* wi = (const float4*)(Wih + (size_t)j * HH);
        const float4* wh = (const float4*)(Whh + (size_t)j * HH);
#pragma unroll 2
        for (int k4 = 0; k4 < 128; k4++) {
            float4 a = wi[k4];
            float4 c = wh[k4];
            int k = k4 * 4;
#pragma unroll
            for (int bb = 0; bb < 8; bb++) {
                ax[bb] += a.x * sx[bb][k] + a.y * sx[bb][k + 1]
                        + a.z * sx[bb][k + 2] + a.w * sx[bb][k + 3];
                ahh[bb] += c.x * sh[bb][k] + c.y * sh[bb][k + 1]
                         + c.z * sh[bb][k + 2] + c.w * sh[bb][k + 3];
            }
        }
        if (gate == 0) {
#pragma unroll
            for (int bb = 0; bb < 8; bb++) r8[bb] = my_sigmoid(ax[bb] + ahh[bb]);
        } else if (gate == 1) {
#pragma unroll
            for (int bb = 0; bb < 8; bb++) z8[bb] = my_sigmoid(ax[bb] + ahh[bb]);
        } else {
#pragma unroll
            for (int bb = 0; bb < 8; bb++) {
                float n = my_tanh(ax[bb] + r8[bb] * ahh[bb]);
                float hn = (1.0f - z8[bb]) * n + z8[bb] * sh[bb][h];
                g_hnew[(b0 + bb) * HH + h] = hn;
                hidden_out[(b0 + bb) * HH + h] = hn;
            }
        }
    }
}

// ---------------- matvec: grid (8 h-tiles, 32 batch-tiles), 8 batches/CTA --
__global__ __launch_bounds__(256) void matvec_kernel(
    const float* __restrict__ M, int ldm, int off,
    const float* __restrict__ vec, float* __restrict__ out) {
    int b0 = blockIdx.y * 8;
    int h0 = blockIdx.x * 64;
    int t = threadIdx.x;
    __shared__ float sv[8][512];
    for (int i = t; i < 4096; i += 256) {
        int bb = i >> 9, k = i & 511;
        sv[bb][k] = vec[(b0 + bb) * HH + k];
    }
    __syncthreads();

    int hl = t >> 2, l4 = t & 3;
    int h = h0 + hl;
    const float* m = M + (size_t)h * ldm + off;
    float acc[8];
#pragma unroll
    for (int bb = 0; bb < 8; bb++) acc[bb] = 0.0f;
    for (int k = l4 * 4; k < HH; k += 16) {
        float4 mv = *(const float4*)(m + k);
#pragma unroll
        for (int bb = 0; bb < 8; bb++) {
            acc[bb] += mv.x * sv[bb][k] + mv.y * sv[bb][k + 1]
                     + mv.z * sv[bb][k + 2] + mv.w * sv[bb][k + 3];
        }
    }
#pragma unroll
    for (int bb = 0; bb < 8; bb++) {
        acc[bb] += __shfl_xor_sync(0xffffffffu, acc[bb], 1);
        acc[bb] += __shfl_xor_sync(0xffffffffu, acc[bb], 2);
    }
    if (l4 == 0) {
#pragma unroll
        for (int bb = 0; bb < 8; bb++) out[(b0 + bb) * HH + h] = acc[bb];
    }
}

// ---------------- softmax ----------------
__global__ void softmax_kernel(const float* __restrict__ scores,
                               float* __restrict__ attns) {
    int b = blockIdx.x;
    int t = threadIdx.x;
    __shared__ float sm[256];
    float v0 = scores[b * SS + t];
    float v1 = scores[b * SS + 256 + t];
    sm[t] = fmaxf(v0, v1);
    __syncthreads();
    for (int off = 128; off > 0; off >>= 1) {
        if (t < off) sm[t] = fmaxf(sm[t], sm[t + off]);
        __syncthreads();
    }
    float mx = sm[0];
    __syncthreads();
    float e0 = __expf(v0 - mx);
    float e1 = __expf(v1 - mx);
    sm[t] = e0 + e1;
    __syncthreads();
    for (int off = 128; off > 0; off >>= 1) {
        if (t < off) sm[t] += sm[t + off];
        __syncthreads();
    }
    float inv = 1.0f / sm[0];
    attns[b * SS + t] = e0 * inv;
    attns[b * SS + 256 + t] = e1 * inv;
}

// ---------------- context ----------------
__global__ void context_kernel(const float* __restrict__ st,
                               const float* __restrict__ attns,
                               float* __restrict__ ctx) {
    int b = blockIdx.y;
    int h0 = blockIdx.x * 8;
    int w = threadIdx.x >> 5, l = threadIdx.x & 31;
    __shared__ float sa[SS];
    for (int s = threadIdx.x; s < SS; s += 256) sa[s] = attns[b * SS + s];
    __syncthreads();
    int h = h0 + w;
    const float* row = st + (size_t)b * HH * SS + (size_t)h * SS;
    float acc = 0.0f;
    for (int s = l * 4; s < SS; s += 128) {
        float4 r4 = *(const float4*)(row + s);
        acc += r4.x * sa[s] + r4.y * sa[s + 1] + r4.z * sa[s + 2] + r4.w * sa[s + 3];
    }
#pragma unroll
    for (int off = 16; off > 0; off >>= 1)
        acc += __shfl_xor_sync(0xffffffffu, acc, off);
    if (l == 0) ctx[b * HH + h] = acc;
}

// ---------------- launch ----------------
extern "C" void kernel_launch(void* const* d_in, const int* in_sizes, int n_in,
                              void* d_out, int out_size) {
    const float* st     = (const float*)d_in[0];
    const float* dy     = (const float*)d_in[1];
    const float* lo     = (const float*)d_in[2];
    const float* lh     = (const float*)d_in[3];
    const float* embW   = (const float*)d_in[4];
    const float* embb   = (const float*)d_in[5];
    const float* Wih    = (const float*)d_in[6];
    const float* Whh    = (const float*)d_in[7];
    const float* bih    = (const float*)d_in[8];
    const float* bhh    = (const float*)d_in[9];
    const float* attn_v = (const float*)d_in[10];
    const float* attn_W = (const float*)d_in[11];
    const float* dec_v  = (const float*)d_in[12];
    const float* dec_W  = (const float*)d_in[13];
    float* out = (float*)d_out;

    float *p_hnew, *p_hc, *p_scores, *p_attns, *p_ctx, *p_cd2;
    cudaGetSymbolAddress((void**)&p_hnew, g_hnew);
    cudaGetSymbolAddress((void**)&p_hc, g_hc);
    cudaGetSymbolAddress((void**)&p_scores, g_scores);
    cudaGetSymbolAddress((void**)&p_attns, g_attns);
    cudaGetSymbolAddress((void**)&p_ctx, g_context);
    cudaGetSymbolAddress((void**)&p_cd2, g_cd2);

    __half *psth, *pdyh, *pWabh, *pWdh;
    cudaGetSymbolAddress((void**)&psth, g_st_hi);
    cudaGetSymbolAddress((void**)&pdyh, g_dy_hi);
    cudaGetSymbolAddress((void**)&pWabh, g_Wab_hi);
    cudaGetSymbolAddress((void**)&pWdh, g_Wd_hi);

    cudaFuncSetAttribute(gemm_fp16_kernel<2>,
                         cudaFuncAttributeMaxDynamicSharedMemorySize, SMEM_BYTES);
    cudaFuncSetAttribute(gemm_fp16_kernel<1>,
                         cudaFuncAttributeMaxDynamicSharedMemorySize, SMEM_BYTES);

    prep_w<<<768, 256>>>(attn_W, dec_W);
    prep_enc<<<4096, 256>>>(st, dy);

    gru_kernel<<<dim3(2, 32), 256>>>(lo, lh, embW, embb, Wih, Whh, bih, bhh,
                                     out + BB * SS);

    matvec_kernel<<<dim3(8, 32), 256>>>(attn_W, H3, 2 * HH, p_hnew, p_hc);

    gemm_fp16_kernel<2><<<dim3(4, BB), 256, SMEM_BYTES>>>(
        pWabh, 1024, psth, pdyh, p_hc, attn_v, p_scores);

    softmax_kernel<<<BB, 256>>>(p_scores, p_attns);
    context_kernel<<<dim3(HH / 8, BB), 256>>>(st, p_attns, p_ctx);

    matvec_kernel<<<dim3(8, 32), 256>>>(dec_W, 2 * HH, HH, p_ctx, p_cd2);

    gemm_fp16_kernel<1><<<dim3(4, BB), 256, SMEM_BYTES>>>(
        pWdh, 512, psth, psth, p_cd2, dec_v, out);
}